// round 10
// baseline (speedup 1.0000x reference)
#include <cuda_runtime.h>
#include <math.h>
#include <stdint.h>

// ---------------- dimensions ----------------
#define BB   2
#define TT   1024
#define CC   768
#define NH   12
#define HD   64
#define LL   4
#define VV   50257
#define NPAD 50304         // 393 * 128, head_w padded rows (transposed)
#define NTOK 2048          // BB*TT
#define BH   24            // BB*NH

// transposed-weight buffer offsets (floats)
#define WQKV_SZ  ((size_t)LL * CC * 3 * CC)
#define WPROJ_SZ ((size_t)LL * CC * CC)
#define WFC_SZ   ((size_t)LL * CC * 4 * CC)
#define WFC2_SZ  ((size_t)LL * 4 * CC * CC)
#define OFF_QKV  0
#define OFF_PROJ (OFF_QKV + WQKV_SZ)
#define OFF_FC   (OFF_PROJ + WPROJ_SZ)
#define OFF_FC2  (OFF_FC + WFC_SZ)
#define WR_TOTAL (OFF_FC2 + WFC2_SZ)

// ---------------- scratch (static device globals; no allocs) ----------------
__device__ float g_x  [NTOK * CC];
__device__ float g_h  [NTOK * CC];
__device__ float g_qkv[NTOK * 3 * CC];
__device__ float g_y  [NTOK * CC];
__device__ float g_m1 [NTOK * 4 * CC];
__device__ float g_wpad[(size_t)NPAD * CC];   // head weights, transposed [NPAD][CC], tf32-rounded
__device__ float g_wr [WR_TOTAL];             // layer weights, transposed [N][K], tf32-rounded

// ---------------- helpers ----------------
__device__ __forceinline__ float warpReduceSum(float v) {
    #pragma unroll
    for (int o = 16; o > 0; o >>= 1) v += __shfl_xor_sync(0xffffffffu, v, o);
    return v;
}
__device__ float blockReduceSum(float v) {
    __shared__ float s[32];
    int lane = threadIdx.x & 31, wid = threadIdx.x >> 5;
    v = warpReduceSum(v);
    if (lane == 0) s[wid] = v;
    __syncthreads();
    int nw = blockDim.x >> 5;
    v = (threadIdx.x < nw) ? s[threadIdx.x] : 0.f;
    if (wid == 0) v = warpReduceSum(v);
    if (threadIdx.x == 0) s[0] = v;
    __syncthreads();
    v = s[0];
    __syncthreads();
    return v;
}

__device__ __forceinline__ float gelu_f(float x) {
    const float k = 0.7978845608028654f;  // sqrt(2/pi)
    float x3 = x * x * x;
    return 0.5f * x * (1.f + tanhf(k * (x + 0.044715f * x3)));
}

__device__ __forceinline__ uint32_t f2tf32(float x) {
    uint32_t r;
    asm("cvt.rna.tf32.f32 %0, %1;" : "=r"(r) : "f"(x));
    return r;
}
__device__ __forceinline__ float roundtf(float x) {
    return __uint_as_float(f2tf32(x));
}

__device__ __forceinline__ void mma_tf32(float c[4],
                                         uint32_t a0, uint32_t a1, uint32_t a2, uint32_t a3,
                                         uint32_t b0, uint32_t b1) {
    asm volatile(
        "mma.sync.aligned.m16n8k8.row.col.f32.tf32.tf32.f32 "
        "{%0,%1,%2,%3}, {%4,%5,%6,%7}, {%8,%9}, {%0,%1,%2,%3};\n"
        : "+f"(c[0]), "+f"(c[1]), "+f"(c[2]), "+f"(c[3])
        : "r"(a0), "r"(a1), "r"(a2), "r"(a3), "r"(b0), "r"(b1));
}

__device__ __forceinline__ void ldsm4(uint32_t r[4], uint32_t addr) {
    asm volatile("ldmatrix.sync.aligned.m8n8.x4.shared.b16 {%0,%1,%2,%3}, [%4];"
        : "=r"(r[0]), "=r"(r[1]), "=r"(r[2]), "=r"(r[3]) : "r"(addr));
}

// ---------------- cp.async helpers ----------------
__device__ __forceinline__ void cp16(uint32_t dst, const void* src) {
    asm volatile("cp.async.cg.shared.global [%0], [%1], 16;" :: "r"(dst), "l"(src));
}
__device__ __forceinline__ void cp_commit() {
    asm volatile("cp.async.commit_group;");
}
__device__ __forceinline__ void cp_wait1() {
    asm volatile("cp.async.wait_group 1;");
}
__device__ __forceinline__ void cp_wait0() {
    asm volatile("cp.async.wait_group 0;");
}

// ---------------- transpose + tf32-round: src[K][N] -> dst[Npad][K] ----------------
__global__ void transpose_round_k(const float* __restrict__ src, float* __restrict__ dst,
                                  int K, int N, int Npad) {
    __shared__ float t[32][33];
    int n0 = blockIdx.x * 32, k0 = blockIdx.y * 32;
    int tx = threadIdx.x, ty = threadIdx.y;   // block (32, 8)
    #pragma unroll
    for (int i = 0; i < 4; i++) {
        int k = k0 + ty + i * 8;
        int n = n0 + tx;
        t[ty + i * 8][tx] = (n < N) ? src[(size_t)k * N + n] : 0.f;
    }
    __syncthreads();
    #pragma unroll
    for (int i = 0; i < 4; i++) {
        int n = n0 + ty + i * 8;
        dst[(size_t)n * K + k0 + tx] = roundtf(t[tx][ty + i * 8]);
    }
}

// ---------------- embedding ----------------
__global__ void embed_k(const int* __restrict__ idx, const float* __restrict__ wte,
                        const float* __restrict__ wpe, float* __restrict__ x) {
    int row = blockIdx.x;              // b*TT + t
    int t = row & (TT - 1);
    int tok = idx[row];
    const float* we = wte + (size_t)tok * CC;
    const float* pe = wpe + (size_t)t * CC;
    float* o = x + (size_t)row * CC;
    for (int c = threadIdx.x; c < CC; c += blockDim.x) o[c] = we[c] + pe[c];
}

// ---------------- layernorm (output tf32-rounded: feeds GEMM A-side) ----------------
__global__ void layernorm_k(const float* __restrict__ in, const float* __restrict__ w,
                            const float* __restrict__ b, float* __restrict__ out) {
    int row = blockIdx.x;
    const float* p = in + (size_t)row * CC;
    int tid = threadIdx.x;
    float v[3];
    float s = 0.f;
    #pragma unroll
    for (int i = 0; i < 3; i++) { v[i] = p[tid + i * 256]; s += v[i]; }
    float mean = blockReduceSum(s) * (1.f / (float)CC);
    float vs = 0.f;
    #pragma unroll
    for (int i = 0; i < 3; i++) { float d = v[i] - mean; vs += d * d; }
    float var = blockReduceSum(vs) * (1.f / (float)CC);
    float rstd = rsqrtf(var + 1e-5f);
    float* o = out + (size_t)row * CC;
    #pragma unroll
    for (int i = 0; i < 3; i++) {
        int c = tid + i * 256;
        o[c] = roundtf((v[i] - mean) * rstd * w[c] + b[c]);
    }
}

// ---------------- TF32 tensor-core GEMM (cp.async + ldmatrix) ----------------
// C[M x Nout] = epi(A[M x K] @ Bt[Ncols x K]^T).
// Block tile (32*MT) x 128, KT=32, 256 threads = 8 warps, warp grid 2(m) x 4(n),
// warp tile (MT*16) x 32 via MT x 4 m16n8k8 MMAs.
// A smem [m][k] stride 36, B smem [n][k] stride 36 (both K-major, ldmatrix-friendly).
// Operands must be tf32-pre-rounded; K multiple of 32; grid = (Ncols/128, M/(32*MT)).
#define KT   32
#define SA   36
#define SROWB (SA * 4)     // 144 bytes per smem row
#define BROWS 128
#define BSZ  (BROWS * SA)

template <int MT, bool BIAS, bool GELU, bool RESID, bool RNDOUT>
__global__ __launch_bounds__(256, 2) void tgemm_k(
    const float* __restrict__ A, const float* __restrict__ Bt,
    const float* __restrict__ bias, const float* __restrict__ resid,
    float* __restrict__ C, int Nout, int K) {
    extern __shared__ float smem[];

    constexpr int ROWS = 32 * MT;          // A rows per block
    constexpr int ASZ  = ROWS * SA;        // floats
    constexpr int STG  = ASZ + BSZ;        // floats per stage
    constexpr int TPR  = 256 / ROWS;       // threads per A row
    constexpr int KCH  = 32 / TPR;         // k floats per thread
    constexpr int NCPA = KCH / 4;          // cp16 per thread for A

    int tid = threadIdx.x;
    int lane = tid & 31;
    int wid = tid >> 5;
    int warp_m = wid >> 2;             // 0..1
    int warp_n = wid & 3;              // 0..3
    int lr = lane >> 2;                // 0..7
    int lc = lane & 3;                 // 0..3

    int row0 = blockIdx.y * ROWS;
    int col0 = blockIdx.x * 128;

    // cp.async mappings
    int aM  = tid / TPR;               // A row in tile
    int aK4 = (tid % TPR) * KCH;       // A k base (floats)
    int bN  = tid >> 1;                // B row (n) in tile, 0..127
    int bK4 = (tid & 1) * 16;          // B k base (floats)

    float acc[MT][4][4];
    #pragma unroll
    for (int i = 0; i < MT; i++)
        #pragma unroll
        for (int j = 0; j < 4; j++)
            #pragma unroll
            for (int q = 0; q < 4; q++) acc[i][j][q] = 0.f;

    const float* aSrcBase = A + (size_t)(row0 + aM) * K + aK4;
    const float* bSrcBase = Bt + (size_t)(col0 + bN) * K + bK4;

    uint32_t smBase = (uint32_t)__cvta_generic_to_shared(smem);

    auto load_stage = [&](int kt, int s) {
        uint32_t base = smBase + (uint32_t)s * (STG * 4);
        {
            uint32_t dst = base + (uint32_t)(aM * SA + aK4) * 4;
            const float* src = aSrcBase + kt;
            #pragma unroll
            for (int u = 0; u < NCPA; u++)
                cp16(dst + u * 16, src + u * 4);
        }
        {
            uint32_t dst = base + (uint32_t)(ASZ + bN * SA + bK4) * 4;
            const float* src = bSrcBase + kt;
            #pragma unroll
            for (int u = 0; u < 4; u++)
                cp16(dst + u * 16, src + u * 4);
        }
    };

    // per-lane ldmatrix address components
    uint32_t aLane = (uint32_t)((lane & 15) * SROWB + (lane >> 4) * 16);
    uint32_t bLane = (uint32_t)(((lane & 7) + ((lane >> 4) & 1) * 8) * SROWB
                                + ((lane >> 3) & 1) * 16);
    uint32_t aWarpOff = (uint32_t)(warp_m * (MT * 16) * SROWB);
    uint32_t bWarpOff = (uint32_t)(ASZ * 4 + warp_n * 32 * SROWB);

    int nIter = K / KT;
    load_stage(0, 0);
    cp_commit();

    for (int it = 0; it < nIter; it++) {
        if (it + 1 < nIter) {
            load_stage((it + 1) * KT, (it + 1) & 1);
            cp_commit();
            cp_wait1();
        } else {
            cp_wait0();
        }
        __syncthreads();

        uint32_t stageBase = smBase + (uint32_t)(it & 1) * (STG * 4);
        uint32_t aBase = stageBase + aWarpOff + aLane;
        uint32_t bBase = stageBase + bWarpOff + bLane;

        #pragma unroll
        for (int ks = 0; ks < 4; ks++) {
            uint32_t koff = (uint32_t)(ks * 32);   // 8 floats = 32 bytes
            uint32_t af[MT][4];
            #pragma unroll
            for (int mt = 0; mt < MT; mt++)
                ldsm4(af[mt], aBase + (uint32_t)(mt * 16 * SROWB) + koff);
            uint32_t bf[2][4];
            #pragma unroll
            for (int p = 0; p < 2; p++)
                ldsm4(bf[p], bBase + (uint32_t)(p * 16 * SROWB) + koff);
            #pragma unroll
            for (int nt = 0; nt < 4; nt++) {
                uint32_t b0 = bf[nt >> 1][(nt & 1) * 2];
                uint32_t b1 = bf[nt >> 1][(nt & 1) * 2 + 1];
                #pragma unroll
                for (int mt = 0; mt < MT; mt++)
                    mma_tf32(acc[mt][nt], af[mt][0], af[mt][1], af[mt][2], af[mt][3], b0, b1);
            }
        }
        __syncthreads();
    }

    // ---- epilogue ----
    #pragma unroll
    for (int mt = 0; mt < MT; mt++) {
        int rbase = row0 + warp_m * (MT * 16) + mt * 16 + lr;
        #pragma unroll
        for (int nt = 0; nt < 4; nt++) {
            int cbase = col0 + warp_n * 32 + nt * 8 + lc * 2;
            #pragma unroll
            for (int half = 0; half < 2; half++) {
                int r = rbase + half * 8;
                #pragma unroll
                for (int q = 0; q < 2; q++) {
                    int c = cbase + q;
                    if (c < Nout) {
                        float v = acc[mt][nt][half * 2 + q];
                        if (BIAS) v += bias[c];
                        if (GELU) v = gelu_f(v);
                        if (RESID) v += resid[(size_t)r * Nout + c];
                        if (RNDOUT) v = roundtf(v);
                        C[(size_t)r * Nout + c] = v;
                    }
                }
            }
        }
    }
}

#define GEMM_SMEM_BYTES(MT) (2 * ((32 * (MT)) * SA + BSZ) * 4)

// ---------------- fused flash attention (fp32, balanced causal pairing) ----------------
// grid (TT/128, BH), block 256. Each block handles query tiles bx and 15-bx
// sequentially -> every block does exactly 17 s-tile iterations.
// Output y is tf32-rounded (feeds proj GEMM A-side).
__global__ __launch_bounds__(256) void flash_attn_k(const float* __restrict__ qkv,
                                                    float* __restrict__ y) {
    __shared__ float Qt [64][64];   // [d][t]
    __shared__ float KPt[64][64];   // phase 1: K^T [d][s]; phase 2: P^T [s][t]
    __shared__ float Vs [64][64];   // [s][d]

    int bh = blockIdx.y;
    int b = bh / NH, h = bh % NH;
    int tid = threadIdx.x;
    int ty = tid >> 4, tx = tid & 15;
    const int NT2 = TT / 64;        // 16

    #pragma unroll
    for (int pass = 0; pass < 2; pass++) {
        int qt = (pass == 0) ? (int)blockIdx.x : (NT2 - 1 - (int)blockIdx.x);
        int t0 = qt * 64;

        #pragma unroll
        for (int u = 0; u < 4; u++) {
            int idx = tid + u * 256;
            int r = idx >> 4;
            int c4 = (idx & 15) * 4;
            const float* qsrc = qkv + (size_t)(b * TT + t0 + r) * (3 * CC) + h * HD + c4;
            float4 qv = *(const float4*)qsrc;
            Qt[c4 + 0][r] = qv.x;
            Qt[c4 + 1][r] = qv.y;
            Qt[c4 + 2][r] = qv.z;
            Qt[c4 + 3][r] = qv.w;
        }

        float m_i[4], l_i[4], acc[4][4];
        #pragma unroll
        for (int i = 0; i < 4; i++) {
            m_i[i] = -1e30f;
            l_i[i] = 0.f;
            #pragma unroll
            for (int j = 0; j < 4; j++) acc[i][j] = 0.f;
        }

        int nTiles = qt + 1;
        for (int st = 0; st < nTiles; st++) {
            int s0 = st * 64;

            __syncthreads();
            #pragma unroll
            for (int u = 0; u < 4; u++) {
                int idx = tid + u * 256;
                int r = idx >> 4;
                int c4 = (idx & 15) * 4;
                const float* ksrc = qkv + (size_t)(b * TT + s0 + r) * (3 * CC) + CC + h * HD + c4;
                float4 kv = *(const float4*)ksrc;
                KPt[c4 + 0][r] = kv.x;
                KPt[c4 + 1][r] = kv.y;
                KPt[c4 + 2][r] = kv.z;
                KPt[c4 + 3][r] = kv.w;
                const float* vsrc = qkv + (size_t)(b * TT + s0 + r) * (3 * CC) + 2 * CC + h * HD + c4;
                *(float4*)&Vs[r][c4] = *(const float4*)vsrc;
            }
            __syncthreads();

            float S[4][4];
            #pragma unroll
            for (int i = 0; i < 4; i++)
                #pragma unroll
                for (int j = 0; j < 4; j++) S[i][j] = 0.f;

            #pragma unroll 8
            for (int d = 0; d < 64; d++) {
                float4 aq = *(float4*)&Qt[d][ty * 4];
                float4 bq = *(float4*)&KPt[d][tx * 4];
                float av[4] = {aq.x, aq.y, aq.z, aq.w};
                float bv[4] = {bq.x, bq.y, bq.z, bq.w};
                #pragma unroll
                for (int i = 0; i < 4; i++)
                    #pragma unroll
                    for (int j = 0; j < 4; j++) S[i][j] += av[i] * bv[j];
            }

            __syncthreads();

            const float scale = 0.125f;
            bool diag = (st == qt);
            #pragma unroll
            for (int i = 0; i < 4; i++) {
                int t = t0 + ty * 4 + i;
                #pragma unroll
                for (int j = 0; j < 4; j++) {
                    float v = S[i][j] * scale;
                    if (diag && (s0 + tx * 4 + j > t)) v = -1e30f;
                    S[i][j] = v;
                }
            }

            #pragma unroll
            for (int i = 0; i < 4; i++) {
                float rmax = fmaxf(fmaxf(S[i][0], S[i][1]), fmaxf(S[i][2], S[i][3]));
                #pragma unroll
                for (int o = 8; o > 0; o >>= 1)
                    rmax = fmaxf(rmax, __shfl_xor_sync(0xffffffffu, rmax, o));
                float mnew = fmaxf(m_i[i], rmax);
                float alpha = __expf(m_i[i] - mnew);
                float rsum = 0.f;
                #pragma unroll
                for (int j = 0; j < 4; j++) {
                    float p = __expf(S[i][j] - mnew);
                    S[i][j] = p;
                    rsum += p;
                }
                #pragma unroll
                for (int o = 8; o > 0; o >>= 1)
                    rsum += __shfl_xor_sync(0xffffffffu, rsum, o);
                l_i[i] = l_i[i] * alpha + rsum;
                m_i[i] = mnew;
                #pragma unroll
                for (int j = 0; j < 4; j++) acc[i][j] *= alpha;
            }

            #pragma unroll
            for (int i = 0; i < 4; i++)
                #pragma unroll
                for (int j = 0; j < 4; j++)
                    KPt[tx * 4 + j][ty * 4 + i] = S[i][j];
            __syncthreads();

            #pragma unroll 8
            for (int k = 0; k < 64; k++) {
                float4 ap = *(float4*)&KPt[k][ty * 4];
                float4 vv = *(float4*)&Vs[k][tx * 4];
                float av[4] = {ap.x, ap.y, ap.z, ap.w};
                float bv[4] = {vv.x, vv.y, vv.z, vv.w};
                #pragma unroll
                for (int i = 0; i < 4; i++)
                    #pragma unroll
                    for (int j = 0; j < 4; j++) acc[i][j] += av[i] * bv[j];
            }
        }

        #pragma unroll
        for (int i = 0; i < 4; i++) {
            float inv = 1.f / l_i[i];
            int t = t0 + ty * 4 + i;
            float* orow = y + (size_t)(b * TT + t) * CC + h * HD;
            #pragma unroll
            for (int j = 0; j < 4; j++) orow[tx * 4 + j] = roundtf(acc[i][j] * inv);
        }
        __syncthreads();
    }
}

// ---------------- host launcher ----------------
extern "C" void kernel_launch(void* const* d_in, const int* in_sizes, int n_in,
                              void* d_out, int out_size) {
    (void)in_sizes; (void)n_in; (void)out_size;
    const int*   idx    = (const int*)  d_in[0];
    const float* wte    = (const float*)d_in[1];
    const float* wpe    = (const float*)d_in[2];
    const float* ln1_w  = (const float*)d_in[3];
    const float* ln1_b  = (const float*)d_in[4];
    const float* qkv_w  = (const float*)d_in[5];
    const float* qkv_b  = (const float*)d_in[6];
    const float* proj_w = (const float*)d_in[7];
    const float* proj_b = (const float*)d_in[8];
    const float* ln2_w  = (const float*)d_in[9];
    const float* ln2_b  = (const float*)d_in[10];
    const float* fc_w   = (const float*)d_in[11];
    const float* fc_b   = (const float*)d_in[12];
    const float* fc2_w  = (const float*)d_in[13];
    const float* fc2_b  = (const float*)d_in[14];
    const float* lnf_w  = (const float*)d_in[15];
    const float* lnf_b  = (const float*)d_in[16];
    const float* head_w = (const float*)d_in[17];
    float* out = (float*)d_out;

    float *x, *h, *qkv, *y, *m1, *wpad, *wr;
    cudaGetSymbolAddress((void**)&x,    g_x);
    cudaGetSymbolAddress((void**)&h,    g_h);
    cudaGetSymbolAddress((void**)&qkv,  g_qkv);
    cudaGetSymbolAddress((void**)&y,    g_y);
    cudaGetSymbolAddress((void**)&m1,   g_m1);
    cudaGetSymbolAddress((void**)&wpad, g_wpad);
    cudaGetSymbolAddress((void**)&wr,   g_wr);

    cudaFuncSetAttribute(tgemm_k<4, true,  false, false, false>, cudaFuncAttributeMaxDynamicSharedMemorySize, GEMM_SMEM_BYTES(4));
    cudaFuncSetAttribute(tgemm_k<4, true,  true,  false, true >, cudaFuncAttributeMaxDynamicSharedMemorySize, GEMM_SMEM_BYTES(4));
    cudaFuncSetAttribute(tgemm_k<4, false, false, false, false>, cudaFuncAttributeMaxDynamicSharedMemorySize, GEMM_SMEM_BYTES(4));
    cudaFuncSetAttribute(tgemm_k<2, true,  false, true,  false>, cudaFuncAttributeMaxDynamicSharedMemorySize, GEMM_SMEM_BYTES(2));

    float* wr_qkv  = wr + OFF_QKV;
    float* wr_proj = wr + OFF_PROJ;
    float* wr_fc   = wr + OFF_FC;
    float* wr_fc2  = wr + OFF_FC2;

    // prep: transpose + tf32-round all GEMM B operands into [N][K]
    for (int l = 0; l < LL; l++) {
        transpose_round_k<<<dim3((3 * CC) / 32, CC / 32), dim3(32, 8)>>>(
            qkv_w + (size_t)l * CC * 3 * CC, wr_qkv + (size_t)l * 3 * CC * CC, CC, 3 * CC, 3 * CC);
        transpose_round_k<<<dim3(CC / 32, CC / 32), dim3(32, 8)>>>(
            proj_w + (size_t)l * CC * CC, wr_proj + (size_t)l * CC * CC, CC, CC, CC);
        transpose_round_k<<<dim3((4 * CC) / 32, CC / 32), dim3(32, 8)>>>(
            fc_w + (size_t)l * CC * 4 * CC, wr_fc + (size_t)l * 4 * CC * CC, CC, 4 * CC, 4 * CC);
        transpose_round_k<<<dim3(CC / 32, (4 * CC) / 32), dim3(32, 8)>>>(
            fc2_w + (size_t)l * 4 * CC * CC, wr_fc2 + (size_t)l * CC * 4 * CC, 4 * CC, CC, CC);
    }
    transpose_round_k<<<dim3(NPAD / 32, CC / 32), dim3(32, 8)>>>(head_w, wpad, CC, VV, NPAD);

    embed_k<<<NTOK, 256>>>(idx, wte, wpe, x);

    for (int l = 0; l < LL; l++) {
        const float* l_ln1w = ln1_w + (size_t)l * CC;
        const float* l_ln1b = ln1_b + (size_t)l * CC;
        const float* l_qkvw = wr_qkv + (size_t)l * 3 * CC * CC;
        const float* l_qkvb = qkv_b + (size_t)l * 3 * CC;
        const float* l_pw   = wr_proj + (size_t)l * CC * CC;
        const float* l_pb   = proj_b + (size_t)l * CC;
        const float* l_ln2w = ln2_w + (size_t)l * CC;
        const float* l_ln2b = ln2_b + (size_t)l * CC;
        const float* l_fcw  = wr_fc + (size_t)l * 4 * CC * CC;
        const float* l_fcb  = fc_b + (size_t)l * 4 * CC;
        const float* l_fc2w = wr_fc2 + (size_t)l * CC * 4 * CC;
        const float* l_fc2b = fc2_b + (size_t)l * CC;

        layernorm_k<<<NTOK, 256>>>(x, l_ln1w, l_ln1b, h);
        tgemm_k<4, true, false, false, false><<<dim3((3 * CC) / 128, NTOK / 128), 256, GEMM_SMEM_BYTES(4)>>>(
            h, l_qkvw, l_qkvb, nullptr, qkv, 3 * CC, CC);
        flash_attn_k<<<dim3(TT / 128, BH), 256>>>(qkv, y);
        tgemm_k<2, true, false, true, false><<<dim3(CC / 128, NTOK / 64), 256, GEMM_SMEM_BYTES(2)>>>(
            y, l_pw, l_pb, x, x, CC, CC);
        layernorm_k<<<NTOK, 256>>>(x, l_ln2w, l_ln2b, h);
        tgemm_k<4, true, true, false, true><<<dim3((4 * CC) / 128, NTOK / 128), 256, GEMM_SMEM_BYTES(4)>>>(
            h, l_fcw, l_fcb, nullptr, m1, 4 * CC, CC);
        tgemm_k<2, true, false, true, false><<<dim3(CC / 128, NTOK / 64), 256, GEMM_SMEM_BYTES(2)>>>(
            m1, l_fc2w, l_fc2b, x, x, CC, 4 * CC);
    }

    layernorm_k<<<NTOK, 256>>>(x, lnf_w, lnf_b, h);
    tgemm_k<4, false, false, false, false><<<dim3(NPAD / 128, NTOK / 128), 256, GEMM_SMEM_BYTES(4)>>>(
        h, wpad, nullptr, nullptr, out, VV, CC);
}

// round 11
// speedup vs baseline: 1.1413x; 1.1413x over previous
#include <cuda_runtime.h>
#include <math.h>
#include <stdint.h>

// ---------------- dimensions ----------------
#define BB   2
#define TT   1024
#define CC   768
#define NH   12
#define HD   64
#define LL   4
#define VV   50257
#define NPAD 50304         // 393 * 128, head_w padded columns
#define NTOK 2048          // BB*TT
#define BH   24            // BB*NH

// weight-rounding buffer offsets (floats)
#define WQKV_SZ  ((size_t)LL * CC * 3 * CC)
#define WPROJ_SZ ((size_t)LL * CC * CC)
#define WFC_SZ   ((size_t)LL * CC * 4 * CC)
#define WFC2_SZ  ((size_t)LL * 4 * CC * CC)
#define OFF_QKV  0
#define OFF_PROJ (OFF_QKV + WQKV_SZ)
#define OFF_FC   (OFF_PROJ + WPROJ_SZ)
#define OFF_FC2  (OFF_FC + WFC_SZ)
#define WR_TOTAL (OFF_FC2 + WFC2_SZ)

// ---------------- scratch (static device globals; no allocs) ----------------
__device__ float g_x  [NTOK * CC];
__device__ float g_h  [NTOK * CC];
__device__ float g_qkv[NTOK * 3 * CC];
__device__ float g_y  [NTOK * CC];
__device__ float g_m1 [NTOK * 4 * CC];
__device__ float g_wpad[(size_t)CC * NPAD];   // padded+rounded head weights [CC][NPAD]
__device__ float g_wr [WR_TOTAL];             // tf32-rounded layer weights [K][N]

// ---------------- helpers ----------------
__device__ __forceinline__ float warpReduceSum(float v) {
    #pragma unroll
    for (int o = 16; o > 0; o >>= 1) v += __shfl_xor_sync(0xffffffffu, v, o);
    return v;
}
__device__ float blockReduceSum(float v) {
    __shared__ float s[32];
    int lane = threadIdx.x & 31, wid = threadIdx.x >> 5;
    v = warpReduceSum(v);
    if (lane == 0) s[wid] = v;
    __syncthreads();
    int nw = blockDim.x >> 5;
    v = (threadIdx.x < nw) ? s[threadIdx.x] : 0.f;
    if (wid == 0) v = warpReduceSum(v);
    if (threadIdx.x == 0) s[0] = v;
    __syncthreads();
    v = s[0];
    __syncthreads();
    return v;
}

__device__ __forceinline__ float gelu_f(float x) {
    const float k = 0.7978845608028654f;  // sqrt(2/pi)
    float x3 = x * x * x;
    return 0.5f * x * (1.f + tanhf(k * (x + 0.044715f * x3)));
}

__device__ __forceinline__ uint32_t f2tf32(float x) {
    uint32_t r;
    asm("cvt.rna.tf32.f32 %0, %1;" : "=r"(r) : "f"(x));
    return r;
}
__device__ __forceinline__ float roundtf(float x) {
    return __uint_as_float(f2tf32(x));
}

__device__ __forceinline__ void mma_tf32(float c[4],
                                         uint32_t a0, uint32_t a1, uint32_t a2, uint32_t a3,
                                         uint32_t b0, uint32_t b1) {
    asm volatile(
        "mma.sync.aligned.m16n8k8.row.col.f32.tf32.tf32.f32 "
        "{%0,%1,%2,%3}, {%4,%5,%6,%7}, {%8,%9}, {%0,%1,%2,%3};\n"
        : "+f"(c[0]), "+f"(c[1]), "+f"(c[2]), "+f"(c[3])
        : "r"(a0), "r"(a1), "r"(a2), "r"(a3), "r"(b0), "r"(b1));
}

__device__ __forceinline__ void ldsm4(uint32_t r[4], uint32_t addr) {
    asm volatile("ldmatrix.sync.aligned.m8n8.x4.shared.b16 {%0,%1,%2,%3}, [%4];"
        : "=r"(r[0]), "=r"(r[1]), "=r"(r[2]), "=r"(r[3]) : "r"(addr));
}

// ---------------- cp.async helpers ----------------
__device__ __forceinline__ void cp16(uint32_t dst, const void* src) {
    asm volatile("cp.async.cg.shared.global [%0], [%1], 16;" :: "r"(dst), "l"(src));
}
__device__ __forceinline__ void cp_commit() {
    asm volatile("cp.async.commit_group;");
}
__device__ __forceinline__ void cp_wait1() {
    asm volatile("cp.async.wait_group 1;");
}
__device__ __forceinline__ void cp_wait0() {
    asm volatile("cp.async.wait_group 0;");
}

// ---------------- tf32 rounding copy (weights prep) ----------------
__global__ void round_tf32_k(const float* __restrict__ src, float* __restrict__ dst,
                             size_t n4) {
    size_t i = (size_t)blockIdx.x * blockDim.x + threadIdx.x;
    if (i >= n4) return;
    float4 v = ((const float4*)src)[i];
    v.x = roundtf(v.x); v.y = roundtf(v.y);
    v.z = roundtf(v.z); v.w = roundtf(v.w);
    ((float4*)dst)[i] = v;
}

// ---------------- head weight pad + round: [768][50257] -> [768][50304] ----------------
__global__ void pad_head_k(const float* __restrict__ w, float* __restrict__ wp) {
    size_t idx = (size_t)blockIdx.x * blockDim.x + threadIdx.x;
    size_t base = idx * 4;
    const size_t tot = (size_t)CC * NPAD;
    if (base >= tot) return;
    int r = (int)(base / NPAD);
    int c = (int)(base % NPAD);
    const float* src = w + (size_t)r * VV;
    float4 v;
    v.x = (c + 0 < VV) ? roundtf(src[c + 0]) : 0.f;
    v.y = (c + 1 < VV) ? roundtf(src[c + 1]) : 0.f;
    v.z = (c + 2 < VV) ? roundtf(src[c + 2]) : 0.f;
    v.w = (c + 3 < VV) ? roundtf(src[c + 3]) : 0.f;
    *(float4*)&wp[base] = v;
}

// ---------------- embedding ----------------
__global__ void embed_k(const int* __restrict__ idx, const float* __restrict__ wte,
                        const float* __restrict__ wpe, float* __restrict__ x) {
    int row = blockIdx.x;              // b*TT + t
    int t = row & (TT - 1);
    int tok = idx[row];
    const float* we = wte + (size_t)tok * CC;
    const float* pe = wpe + (size_t)t * CC;
    float* o = x + (size_t)row * CC;
    for (int c = threadIdx.x; c < CC; c += blockDim.x) o[c] = we[c] + pe[c];
}

// ---------------- layernorm (output tf32-rounded: feeds GEMM A-side) ----------------
__global__ void layernorm_k(const float* __restrict__ in, const float* __restrict__ w,
                            const float* __restrict__ b, float* __restrict__ out) {
    int row = blockIdx.x;
    const float* p = in + (size_t)row * CC;
    int tid = threadIdx.x;
    float v[3];
    float s = 0.f;
    #pragma unroll
    for (int i = 0; i < 3; i++) { v[i] = p[tid + i * 256]; s += v[i]; }
    float mean = blockReduceSum(s) * (1.f / (float)CC);
    float vs = 0.f;
    #pragma unroll
    for (int i = 0; i < 3; i++) { float d = v[i] - mean; vs += d * d; }
    float var = blockReduceSum(vs) * (1.f / (float)CC);
    float rstd = rsqrtf(var + 1e-5f);
    float* o = out + (size_t)row * CC;
    #pragma unroll
    for (int i = 0; i < 3; i++) {
        int c = tid + i * 256;
        o[c] = roundtf((v[i] - mean) * rstd * w[c] + b[c]);
    }
}

// ---------------- TF32 tensor-core GEMM (3-stage cp.async + A-ldmatrix) ----------------
// C[M x Nout] = epi(A[M x K] @ B[K x ldB] restricted to Nout cols).
// Operands MUST already be tf32-rounded in gmem (no cvt in mainloop).
// Block tile (32*MT) x 128, KT=32, 256 threads = 8 warps, warp grid 2(m) x 4(n),
// warp tile (MT*16) x 32 via MT x 4 m16n8k8 MMAs.
// A smem [m][k] stride 36 (A frags via ldmatrix.x4); B smem [k][n] stride 132
// (scalar frag LDS, but gmem-coalesced row loads). ldB multiple of 128.
// 3-stage pipeline, one __syncthreads per K-tile.
#define KT   32
#define SA   36
#define SROWB (SA * 4)     // 144 bytes per A smem row
#define SB   132
#define BSZ  (KT * SB)

template <int MT, bool BIAS, bool GELU, bool RESID, bool RNDOUT>
__global__ __launch_bounds__(256, 2) void tgemm_k(
    const float* __restrict__ A, const float* __restrict__ B,
    const float* __restrict__ bias, const float* __restrict__ resid,
    float* __restrict__ C, int M, int Nout, int ldB, int K) {
    extern __shared__ float smem[];

    constexpr int ROWS = 32 * MT;          // A rows per block
    constexpr int ASZ  = ROWS * SA;        // floats
    constexpr int STG  = ASZ + BSZ;        // floats per stage
    constexpr uint32_t STGB = STG * 4;     // bytes per stage
    constexpr int TPR  = 256 / ROWS;       // threads per A row
    constexpr int KCH  = 32 / TPR;         // k floats per thread
    constexpr int NCPA = KCH / 4;          // cp16 per thread for A

    int tid = threadIdx.x;
    int lane = tid & 31;
    int wid = tid >> 5;
    int warp_m = wid >> 2;             // 0..1
    int warp_n = wid & 3;              // 0..3
    int lr = lane >> 2;                // 0..7
    int lc = lane & 3;                 // 0..3

    int row0 = blockIdx.y * ROWS;
    int col0 = blockIdx.x * 128;

    int aM  = tid / TPR;               // A row in tile
    int aK4 = (tid % TPR) * KCH;       // A k base
    int bK  = tid >> 3;                // 0..31 (B row)
    int bN4 = (tid & 7) * 4;           // B n base (+u*32)

    float acc[MT][4][4];
    #pragma unroll
    for (int i = 0; i < MT; i++)
        #pragma unroll
        for (int j = 0; j < 4; j++)
            #pragma unroll
            for (int q = 0; q < 4; q++) acc[i][j][q] = 0.f;

    const float* aSrcBase = A + (size_t)(row0 + aM) * K + aK4;
    const float* bSrcBase = B + (size_t)bK * ldB + col0 + bN4;

    uint32_t smBase = (uint32_t)__cvta_generic_to_shared(smem);

    auto load_stage = [&](int kt, int s) {
        uint32_t base = smBase + (uint32_t)s * STGB;
        {
            uint32_t dst = base + (uint32_t)(aM * SA + aK4) * 4;
            const float* src = aSrcBase + kt;
            #pragma unroll
            for (int u = 0; u < NCPA; u++)
                cp16(dst + u * 16, src + u * 4);
        }
        {
            uint32_t dst = base + (uint32_t)(ASZ + bK * SB + bN4) * 4;
            const float* src = bSrcBase + (size_t)kt * ldB;
            #pragma unroll
            for (int u = 0; u < 4; u++)
                cp16(dst + u * 32 * 4, src + u * 32);
        }
    };

    // per-lane ldmatrix address for A (verified bit-exact in prior round)
    uint32_t aLane = (uint32_t)((lane & 15) * SROWB + (lane >> 4) * 16);
    uint32_t aWarpOff = (uint32_t)(warp_m * (MT * 16) * SROWB);

    int nIter = K / KT;
    load_stage(0, 0);
    cp_commit();
    load_stage(KT, 1);
    cp_commit();

    for (int it = 0; it < nIter; it++) {
        if (it + 1 < nIter) cp_wait1(); else cp_wait0();
        __syncthreads();

        uint32_t stageBase = smBase + (uint32_t)(it % 3) * STGB;
        uint32_t aBase = stageBase + aWarpOff + aLane;
        const uint32_t* Bs = (const uint32_t*)smem + (size_t)(it % 3) * STG + ASZ;

        #pragma unroll
        for (int ks = 0; ks < 4; ks++) {
            int k0 = ks * 8;
            uint32_t af[MT][4];
            #pragma unroll
            for (int mt = 0; mt < MT; mt++)
                ldsm4(af[mt], aBase + (uint32_t)(mt * 16 * SROWB + ks * 32));
            #pragma unroll
            for (int nt = 0; nt < 4; nt++) {
                int bn = warp_n * 32 + nt * 8;
                uint32_t b0 = Bs[(k0 + lc    ) * SB + bn + lr];
                uint32_t b1 = Bs[(k0 + 4 + lc) * SB + bn + lr];
                #pragma unroll
                for (int mt = 0; mt < MT; mt++)
                    mma_tf32(acc[mt][nt], af[mt][0], af[mt][1], af[mt][2], af[mt][3], b0, b1);
            }
        }

        if (it + 2 < nIter) {
            load_stage((it + 2) * KT, (it + 2) % 3);
            cp_commit();
        }
    }

    // ---- epilogue ----
    #pragma unroll
    for (int mt = 0; mt < MT; mt++) {
        int rbase = row0 + warp_m * (MT * 16) + mt * 16 + lr;
        #pragma unroll
        for (int nt = 0; nt < 4; nt++) {
            int cbase = col0 + warp_n * 32 + nt * 8 + lc * 2;
            #pragma unroll
            for (int half = 0; half < 2; half++) {
                int r = rbase + half * 8;
                #pragma unroll
                for (int q = 0; q < 2; q++) {
                    int c = cbase + q;
                    if (c < Nout) {
                        float v = acc[mt][nt][half * 2 + q];
                        if (BIAS) v += bias[c];
                        if (GELU) v = gelu_f(v);
                        if (RESID) v += resid[(size_t)r * Nout + c];
                        if (RNDOUT) v = roundtf(v);
                        C[(size_t)r * Nout + c] = v;
                    }
                }
            }
        }
    }
}

#define GEMM_SMEM_BYTES(MT) (3 * ((32 * (MT)) * SA + BSZ) * 4)

// ---------------- fused flash attention (fp32, balanced causal pairing) ----------------
// grid (TT/128, BH), block 256. Each block handles query tiles bx and 15-bx
// sequentially -> every block does exactly 17 s-tile iterations.
// Output y is tf32-rounded (feeds proj GEMM A-side).
__global__ __launch_bounds__(256) void flash_attn_k(const float* __restrict__ qkv,
                                                    float* __restrict__ y) {
    __shared__ float Qt [64][64];   // [d][t]
    __shared__ float KPt[64][64];   // phase 1: K^T [d][s]; phase 2: P^T [s][t]
    __shared__ float Vs [64][64];   // [s][d]

    int bh = blockIdx.y;
    int b = bh / NH, h = bh % NH;
    int tid = threadIdx.x;
    int ty = tid >> 4, tx = tid & 15;
    const int NT2 = TT / 64;        // 16

    #pragma unroll
    for (int pass = 0; pass < 2; pass++) {
        int qt = (pass == 0) ? (int)blockIdx.x : (NT2 - 1 - (int)blockIdx.x);
        int t0 = qt * 64;

        #pragma unroll
        for (int u = 0; u < 4; u++) {
            int idx = tid + u * 256;
            int r = idx >> 4;
            int c4 = (idx & 15) * 4;
            const float* qsrc = qkv + (size_t)(b * TT + t0 + r) * (3 * CC) + h * HD + c4;
            float4 qv = *(const float4*)qsrc;
            Qt[c4 + 0][r] = qv.x;
            Qt[c4 + 1][r] = qv.y;
            Qt[c4 + 2][r] = qv.z;
            Qt[c4 + 3][r] = qv.w;
        }

        float m_i[4], l_i[4], acc[4][4];
        #pragma unroll
        for (int i = 0; i < 4; i++) {
            m_i[i] = -1e30f;
            l_i[i] = 0.f;
            #pragma unroll
            for (int j = 0; j < 4; j++) acc[i][j] = 0.f;
        }

        int nTiles = qt + 1;
        for (int st = 0; st < nTiles; st++) {
            int s0 = st * 64;

            __syncthreads();
            #pragma unroll
            for (int u = 0; u < 4; u++) {
                int idx = tid + u * 256;
                int r = idx >> 4;
                int c4 = (idx & 15) * 4;
                const float* ksrc = qkv + (size_t)(b * TT + s0 + r) * (3 * CC) + CC + h * HD + c4;
                float4 kv = *(const float4*)ksrc;
                KPt[c4 + 0][r] = kv.x;
                KPt[c4 + 1][r] = kv.y;
                KPt[c4 + 2][r] = kv.z;
                KPt[c4 + 3][r] = kv.w;
                const float* vsrc = qkv + (size_t)(b * TT + s0 + r) * (3 * CC) + 2 * CC + h * HD + c4;
                *(float4*)&Vs[r][c4] = *(const float4*)vsrc;
            }
            __syncthreads();

            float S[4][4];
            #pragma unroll
            for (int i = 0; i < 4; i++)
                #pragma unroll
                for (int j = 0; j < 4; j++) S[i][j] = 0.f;

            #pragma unroll 8
            for (int d = 0; d < 64; d++) {
                float4 aq = *(float4*)&Qt[d][ty * 4];
                float4 bq = *(float4*)&KPt[d][tx * 4];
                float av[4] = {aq.x, aq.y, aq.z, aq.w};
                float bv[4] = {bq.x, bq.y, bq.z, bq.w};
                #pragma unroll
                for (int i = 0; i < 4; i++)
                    #pragma unroll
                    for (int j = 0; j < 4; j++) S[i][j] += av[i] * bv[j];
            }

            __syncthreads();

            const float scale = 0.125f;
            bool diag = (st == qt);
            #pragma unroll
            for (int i = 0; i < 4; i++) {
                int t = t0 + ty * 4 + i;
                #pragma unroll
                for (int j = 0; j < 4; j++) {
                    float v = S[i][j] * scale;
                    if (diag && (s0 + tx * 4 + j > t)) v = -1e30f;
                    S[i][j] = v;
                }
            }

            #pragma unroll
            for (int i = 0; i < 4; i++) {
                float rmax = fmaxf(fmaxf(S[i][0], S[i][1]), fmaxf(S[i][2], S[i][3]));
                #pragma unroll
                for (int o = 8; o > 0; o >>= 1)
                    rmax = fmaxf(rmax, __shfl_xor_sync(0xffffffffu, rmax, o));
                float mnew = fmaxf(m_i[i], rmax);
                float alpha = __expf(m_i[i] - mnew);
                float rsum = 0.f;
                #pragma unroll
                for (int j = 0; j < 4; j++) {
                    float p = __expf(S[i][j] - mnew);
                    S[i][j] = p;
                    rsum += p;
                }
                #pragma unroll
                for (int o = 8; o > 0; o >>= 1)
                    rsum += __shfl_xor_sync(0xffffffffu, rsum, o);
                l_i[i] = l_i[i] * alpha + rsum;
                m_i[i] = mnew;
                #pragma unroll
                for (int j = 0; j < 4; j++) acc[i][j] *= alpha;
            }

            #pragma unroll
            for (int i = 0; i < 4; i++)
                #pragma unroll
                for (int j = 0; j < 4; j++)
                    KPt[tx * 4 + j][ty * 4 + i] = S[i][j];
            __syncthreads();

            #pragma unroll 8
            for (int k = 0; k < 64; k++) {
                float4 ap = *(float4*)&KPt[k][ty * 4];
                float4 vv = *(float4*)&Vs[k][tx * 4];
                float av[4] = {ap.x, ap.y, ap.z, ap.w};
                float bv[4] = {vv.x, vv.y, vv.z, vv.w};
                #pragma unroll
                for (int i = 0; i < 4; i++)
                    #pragma unroll
                    for (int j = 0; j < 4; j++) acc[i][j] += av[i] * bv[j];
            }
        }

        #pragma unroll
        for (int i = 0; i < 4; i++) {
            float inv = 1.f / l_i[i];
            int t = t0 + ty * 4 + i;
            float* orow = y + (size_t)(b * TT + t) * CC + h * HD;
            #pragma unroll
            for (int j = 0; j < 4; j++) orow[tx * 4 + j] = roundtf(acc[i][j] * inv);
        }
        __syncthreads();
    }
}

// ---------------- host launcher ----------------
extern "C" void kernel_launch(void* const* d_in, const int* in_sizes, int n_in,
                              void* d_out, int out_size) {
    (void)in_sizes; (void)n_in; (void)out_size;
    const int*   idx    = (const int*)  d_in[0];
    const float* wte    = (const float*)d_in[1];
    const float* wpe    = (const float*)d_in[2];
    const float* ln1_w  = (const float*)d_in[3];
    const float* ln1_b  = (const float*)d_in[4];
    const float* qkv_w  = (const float*)d_in[5];
    const float* qkv_b  = (const float*)d_in[6];
    const float* proj_w = (const float*)d_in[7];
    const float* proj_b = (const float*)d_in[8];
    const float* ln2_w  = (const float*)d_in[9];
    const float* ln2_b  = (const float*)d_in[10];
    const float* fc_w   = (const float*)d_in[11];
    const float* fc_b   = (const float*)d_in[12];
    const float* fc2_w  = (const float*)d_in[13];
    const float* fc2_b  = (const float*)d_in[14];
    const float* lnf_w  = (const float*)d_in[15];
    const float* lnf_b  = (const float*)d_in[16];
    const float* head_w = (const float*)d_in[17];
    float* out = (float*)d_out;

    float *x, *h, *qkv, *y, *m1, *wpad, *wr;
    cudaGetSymbolAddress((void**)&x,    g_x);
    cudaGetSymbolAddress((void**)&h,    g_h);
    cudaGetSymbolAddress((void**)&qkv,  g_qkv);
    cudaGetSymbolAddress((void**)&y,    g_y);
    cudaGetSymbolAddress((void**)&m1,   g_m1);
    cudaGetSymbolAddress((void**)&wpad, g_wpad);
    cudaGetSymbolAddress((void**)&wr,   g_wr);

    cudaFuncSetAttribute(tgemm_k<4, true,  false, false, false>, cudaFuncAttributeMaxDynamicSharedMemorySize, GEMM_SMEM_BYTES(4));
    cudaFuncSetAttribute(tgemm_k<4, true,  true,  false, true >, cudaFuncAttributeMaxDynamicSharedMemorySize, GEMM_SMEM_BYTES(4));
    cudaFuncSetAttribute(tgemm_k<4, false, false, false, false>, cudaFuncAttributeMaxDynamicSharedMemorySize, GEMM_SMEM_BYTES(4));
    cudaFuncSetAttribute(tgemm_k<2, true,  false, true,  false>, cudaFuncAttributeMaxDynamicSharedMemorySize, GEMM_SMEM_BYTES(2));

    float* wr_qkv  = wr + OFF_QKV;
    float* wr_proj = wr + OFF_PROJ;
    float* wr_fc   = wr + OFF_FC;
    float* wr_fc2  = wr + OFF_FC2;

    // prep: round weights to tf32 once per launch (layout unchanged [K][N])
    round_tf32_k<<<(int)((WQKV_SZ  / 4 + 255) / 256), 256>>>(qkv_w,  wr_qkv,  WQKV_SZ  / 4);
    round_tf32_k<<<(int)((WPROJ_SZ / 4 + 255) / 256), 256>>>(proj_w, wr_proj, WPROJ_SZ / 4);
    round_tf32_k<<<(int)((WFC_SZ   / 4 + 255) / 256), 256>>>(fc_w,   wr_fc,   WFC_SZ   / 4);
    round_tf32_k<<<(int)((WFC2_SZ  / 4 + 255) / 256), 256>>>(fc2_w,  wr_fc2,  WFC2_SZ  / 4);
    {
        size_t tot4 = ((size_t)CC * NPAD) / 4;
        pad_head_k<<<(int)((tot4 + 255) / 256), 256>>>(head_w, wpad);
    }

    embed_k<<<NTOK, 256>>>(idx, wte, wpe, x);

    for (int l = 0; l < LL; l++) {
        const float* l_ln1w  = ln1_w  + (size_t)l * CC;
        const float* l_ln1b  = ln1_b  + (size_t)l * CC;
        const float* l_qkvw  = wr_qkv  + (size_t)l * CC * 3 * CC;
        const float* l_qkvb  = qkv_b  + (size_t)l * 3 * CC;
        const float* l_pw    = wr_proj + (size_t)l * CC * CC;
        const float* l_pb    = proj_b + (size_t)l * CC;
        const float* l_ln2w  = ln2_w  + (size_t)l * CC;
        const float* l_ln2b  = ln2_b  + (size_t)l * CC;
        const float* l_fcw   = wr_fc   + (size_t)l * CC * 4 * CC;
        const float* l_fcb   = fc_b   + (size_t)l * 4 * CC;
        const float* l_fc2w  = wr_fc2  + (size_t)l * 4 * CC * CC;
        const float* l_fc2b  = fc2_b  + (size_t)l * CC;

        layernorm_k<<<NTOK, 256>>>(x, l_ln1w, l_ln1b, h);
        tgemm_k<4, true, false, false, false><<<dim3((3 * CC) / 128, NTOK / 128), 256, GEMM_SMEM_BYTES(4)>>>(
            h, l_qkvw, l_qkvb, nullptr, qkv, NTOK, 3 * CC, 3 * CC, CC);
        flash_attn_k<<<dim3(TT / 128, BH), 256>>>(qkv, y);
        tgemm_k<2, true, false, true, false><<<dim3(CC / 128, NTOK / 64), 256, GEMM_SMEM_BYTES(2)>>>(
            y, l_pw, l_pb, x, x, NTOK, CC, CC, CC);
        layernorm_k<<<NTOK, 256>>>(x, l_ln2w, l_ln2b, h);
        tgemm_k<4, true, true, false, true><<<dim3((4 * CC) / 128, NTOK / 128), 256, GEMM_SMEM_BYTES(4)>>>(
            h, l_fcw, l_fcb, nullptr, m1, NTOK, 4 * CC, 4 * CC, CC);
        tgemm_k<2, true, false, true, false><<<dim3(CC / 128, NTOK / 64), 256, GEMM_SMEM_BYTES(2)>>>(
            m1, l_fc2w, l_fc2b, x, x, NTOK, CC, CC, 4 * CC);
    }

    layernorm_k<<<NTOK, 256>>>(x, lnf_w, lnf_b, h);
    tgemm_k<4, false, false, false, false><<<dim3(NPAD / 128, NTOK / 128), 256, GEMM_SMEM_BYTES(4)>>>(
        h, wpad, nullptr, nullptr, out, NTOK, VV, NPAD, CC);
}

// round 12
// speedup vs baseline: 1.2629x; 1.1065x over previous
#include <cuda_runtime.h>
#include <math.h>
#include <stdint.h>

// ---------------- dimensions ----------------
#define BB   2
#define TT   1024
#define CC   768
#define NH   12
#define HD   64
#define LL   4
#define VV   50257
#define NPAD 50304         // 393 * 128, head_w padded columns
#define NTOK 2048          // BB*TT
#define BH   24            // BB*NH

// weight-rounding buffer offsets (floats)
#define WQKV_SZ  ((size_t)LL * CC * 3 * CC)
#define WPROJ_SZ ((size_t)LL * CC * CC)
#define WFC_SZ   ((size_t)LL * CC * 4 * CC)
#define WFC2_SZ  ((size_t)LL * 4 * CC * CC)
#define OFF_QKV  0
#define OFF_PROJ (OFF_QKV + WQKV_SZ)
#define OFF_FC   (OFF_PROJ + WPROJ_SZ)
#define OFF_FC2  (OFF_FC + WFC_SZ)
#define WR_TOTAL (OFF_FC2 + WFC2_SZ)

// ---------------- scratch (static device globals; no allocs) ----------------
__device__ float g_x  [NTOK * CC];
__device__ float g_h  [NTOK * CC];
__device__ float g_qkv[NTOK * 3 * CC];
__device__ float g_y  [NTOK * CC];
__device__ float g_m1 [NTOK * 4 * CC];
__device__ float g_wpad[(size_t)CC * NPAD];   // padded+rounded head weights [CC][NPAD]
__device__ float g_wr [WR_TOTAL];             // tf32-rounded layer weights [K][N]

// ---------------- helpers ----------------
__device__ __forceinline__ float warpReduceSum(float v) {
    #pragma unroll
    for (int o = 16; o > 0; o >>= 1) v += __shfl_xor_sync(0xffffffffu, v, o);
    return v;
}
__device__ float blockReduceSum(float v) {
    __shared__ float s[32];
    int lane = threadIdx.x & 31, wid = threadIdx.x >> 5;
    v = warpReduceSum(v);
    if (lane == 0) s[wid] = v;
    __syncthreads();
    int nw = blockDim.x >> 5;
    v = (threadIdx.x < nw) ? s[threadIdx.x] : 0.f;
    if (wid == 0) v = warpReduceSum(v);
    if (threadIdx.x == 0) s[0] = v;
    __syncthreads();
    v = s[0];
    __syncthreads();
    return v;
}

__device__ __forceinline__ float gelu_f(float x) {
    const float k = 0.7978845608028654f;  // sqrt(2/pi)
    float x3 = x * x * x;
    return 0.5f * x * (1.f + tanhf(k * (x + 0.044715f * x3)));
}

__device__ __forceinline__ uint32_t f2tf32(float x) {
    uint32_t r;
    asm("cvt.rna.tf32.f32 %0, %1;" : "=r"(r) : "f"(x));
    return r;
}
__device__ __forceinline__ float roundtf(float x) {
    return __uint_as_float(f2tf32(x));
}

__device__ __forceinline__ void mma_tf32(float c[4],
                                         uint32_t a0, uint32_t a1, uint32_t a2, uint32_t a3,
                                         uint32_t b0, uint32_t b1) {
    asm volatile(
        "mma.sync.aligned.m16n8k8.row.col.f32.tf32.tf32.f32 "
        "{%0,%1,%2,%3}, {%4,%5,%6,%7}, {%8,%9}, {%0,%1,%2,%3};\n"
        : "+f"(c[0]), "+f"(c[1]), "+f"(c[2]), "+f"(c[3])
        : "r"(a0), "r"(a1), "r"(a2), "r"(a3), "r"(b0), "r"(b1));
}

__device__ __forceinline__ void ldsm4(uint32_t r[4], uint32_t addr) {
    asm volatile("ldmatrix.sync.aligned.m8n8.x4.shared.b16 {%0,%1,%2,%3}, [%4];"
        : "=r"(r[0]), "=r"(r[1]), "=r"(r[2]), "=r"(r[3]) : "r"(addr));
}

// ---------------- cp.async helpers ----------------
__device__ __forceinline__ void cp16(uint32_t dst, const void* src) {
    asm volatile("cp.async.cg.shared.global [%0], [%1], 16;" :: "r"(dst), "l"(src));
}
__device__ __forceinline__ void cp_commit() {
    asm volatile("cp.async.commit_group;");
}
__device__ __forceinline__ void cp_wait1() {
    asm volatile("cp.async.wait_group 1;");
}
__device__ __forceinline__ void cp_wait0() {
    asm volatile("cp.async.wait_group 0;");
}

// ---------------- tf32 rounding copy (weights prep) ----------------
__global__ void round_tf32_k(const float* __restrict__ src, float* __restrict__ dst,
                             size_t n4) {
    size_t i = (size_t)blockIdx.x * blockDim.x + threadIdx.x;
    if (i >= n4) return;
    float4 v = ((const float4*)src)[i];
    v.x = roundtf(v.x); v.y = roundtf(v.y);
    v.z = roundtf(v.z); v.w = roundtf(v.w);
    ((float4*)dst)[i] = v;
}

// ---------------- head weight pad + round: [768][50257] -> [768][50304] ----------------
__global__ void pad_head_k(const float* __restrict__ w, float* __restrict__ wp) {
    size_t idx = (size_t)blockIdx.x * blockDim.x + threadIdx.x;
    size_t base = idx * 4;
    const size_t tot = (size_t)CC * NPAD;
    if (base >= tot) return;
    int r = (int)(base / NPAD);
    int c = (int)(base % NPAD);
    const float* src = w + (size_t)r * VV;
    float4 v;
    v.x = (c + 0 < VV) ? roundtf(src[c + 0]) : 0.f;
    v.y = (c + 1 < VV) ? roundtf(src[c + 1]) : 0.f;
    v.z = (c + 2 < VV) ? roundtf(src[c + 2]) : 0.f;
    v.w = (c + 3 < VV) ? roundtf(src[c + 3]) : 0.f;
    *(float4*)&wp[base] = v;
}

// ---------------- embedding ----------------
__global__ void embed_k(const int* __restrict__ idx, const float* __restrict__ wte,
                        const float* __restrict__ wpe, float* __restrict__ x) {
    int row = blockIdx.x;              // b*TT + t
    int t = row & (TT - 1);
    int tok = idx[row];
    const float* we = wte + (size_t)tok * CC;
    const float* pe = wpe + (size_t)t * CC;
    float* o = x + (size_t)row * CC;
    for (int c = threadIdx.x; c < CC; c += blockDim.x) o[c] = we[c] + pe[c];
}

// ---------------- layernorm (output tf32-rounded: feeds GEMM A-side) ----------------
__global__ void layernorm_k(const float* __restrict__ in, const float* __restrict__ w,
                            const float* __restrict__ b, float* __restrict__ out) {
    int row = blockIdx.x;
    const float* p = in + (size_t)row * CC;
    int tid = threadIdx.x;
    float v[3];
    float s = 0.f;
    #pragma unroll
    for (int i = 0; i < 3; i++) { v[i] = p[tid + i * 256]; s += v[i]; }
    float mean = blockReduceSum(s) * (1.f / (float)CC);
    float vs = 0.f;
    #pragma unroll
    for (int i = 0; i < 3; i++) { float d = v[i] - mean; vs += d * d; }
    float var = blockReduceSum(vs) * (1.f / (float)CC);
    float rstd = rsqrtf(var + 1e-5f);
    float* o = out + (size_t)row * CC;
    #pragma unroll
    for (int i = 0; i < 3; i++) {
        int c = tid + i * 256;
        o[c] = roundtf((v[i] - mean) * rstd * w[c] + b[c]);
    }
}

// ---------------- TF32 tensor-core GEMM (3-stage cp.async + A-ldmatrix) ----------------
// C[M x Nout] = epi(A[M x K] @ B[K x ldB] restricted to Nout cols).
// Operands MUST already be tf32-rounded in gmem (no cvt in mainloop).
// Block tile (32*MT) x 128, KT=32, 256 threads = 8 warps, warp grid 2(m) x 4(n),
// warp tile (MT*16) x 32 via MT x 4 m16n8k8 MMAs.
// A smem [m][k] stride 36 (A frags via ldmatrix.x4); B smem [k][n] stride 136
// (conflict-free scalar frag LDS, gmem-coalesced row loads). ldB multiple of 128.
// GRID: x = row tile (fast -> L2 reuse of B across row blocks), y = col tile.
// 3-stage pipeline, one __syncthreads per K-tile.
#define KT   32
#define SA   36
#define SROWB (SA * 4)     // 144 bytes per A smem row
#define SB   136           // stride%32==8 -> B frag banks 8*lc+lr all distinct
#define BSZ  (KT * SB)

template <int MT, bool BIAS, bool GELU, bool RESID, bool RNDOUT>
__global__ __launch_bounds__(256, 2) void tgemm_k(
    const float* __restrict__ A, const float* __restrict__ B,
    const float* __restrict__ bias, const float* __restrict__ resid,
    float* __restrict__ C, int M, int Nout, int ldB, int K) {
    extern __shared__ float smem[];

    constexpr int ROWS = 32 * MT;          // A rows per block
    constexpr int ASZ  = ROWS * SA;        // floats
    constexpr int STG  = ASZ + BSZ;        // floats per stage
    constexpr uint32_t STGB = STG * 4;     // bytes per stage
    constexpr int TPR  = 256 / ROWS;       // threads per A row
    constexpr int KCH  = 32 / TPR;         // k floats per thread
    constexpr int NCPA = KCH / 4;          // cp16 per thread for A

    int tid = threadIdx.x;
    int lane = tid & 31;
    int wid = tid >> 5;
    int warp_m = wid >> 2;             // 0..1
    int warp_n = wid & 3;              // 0..3
    int lr = lane >> 2;                // 0..7
    int lc = lane & 3;                 // 0..3

    int row0 = blockIdx.x * ROWS;      // row tile on FAST grid axis (L2 B reuse)
    int col0 = blockIdx.y * 128;

    int aM  = tid / TPR;               // A row in tile
    int aK4 = (tid % TPR) * KCH;       // A k base
    int bK  = tid >> 3;                // 0..31 (B row)
    int bN4 = (tid & 7) * 4;           // B n base (+u*32)

    float acc[MT][4][4];
    #pragma unroll
    for (int i = 0; i < MT; i++)
        #pragma unroll
        for (int j = 0; j < 4; j++)
            #pragma unroll
            for (int q = 0; q < 4; q++) acc[i][j][q] = 0.f;

    const float* aSrcBase = A + (size_t)(row0 + aM) * K + aK4;
    const float* bSrcBase = B + (size_t)bK * ldB + col0 + bN4;

    uint32_t smBase = (uint32_t)__cvta_generic_to_shared(smem);

    auto load_stage = [&](int kt, int s) {
        uint32_t base = smBase + (uint32_t)s * STGB;
        {
            uint32_t dst = base + (uint32_t)(aM * SA + aK4) * 4;
            const float* src = aSrcBase + kt;
            #pragma unroll
            for (int u = 0; u < NCPA; u++)
                cp16(dst + u * 16, src + u * 4);
        }
        {
            uint32_t dst = base + (uint32_t)(ASZ + bK * SB + bN4) * 4;
            const float* src = bSrcBase + (size_t)kt * ldB;
            #pragma unroll
            for (int u = 0; u < 4; u++)
                cp16(dst + u * 32 * 4, src + u * 32);
        }
    };

    // per-lane ldmatrix address for A (verified bit-exact in prior rounds)
    uint32_t aLane = (uint32_t)((lane & 15) * SROWB + (lane >> 4) * 16);
    uint32_t aWarpOff = (uint32_t)(warp_m * (MT * 16) * SROWB);

    int nIter = K / KT;
    load_stage(0, 0);
    cp_commit();
    load_stage(KT, 1);
    cp_commit();

    for (int it = 0; it < nIter; it++) {
        if (it + 1 < nIter) cp_wait1(); else cp_wait0();
        __syncthreads();

        uint32_t stageBase = smBase + (uint32_t)(it % 3) * STGB;
        uint32_t aBase = stageBase + aWarpOff + aLane;
        const uint32_t* Bs = (const uint32_t*)smem + (size_t)(it % 3) * STG + ASZ;

        #pragma unroll
        for (int ks = 0; ks < 4; ks++) {
            int k0 = ks * 8;
            uint32_t af[MT][4];
            #pragma unroll
            for (int mt = 0; mt < MT; mt++)
                ldsm4(af[mt], aBase + (uint32_t)(mt * 16 * SROWB + ks * 32));
            #pragma unroll
            for (int nt = 0; nt < 4; nt++) {
                int bn = warp_n * 32 + nt * 8;
                uint32_t b0 = Bs[(k0 + lc    ) * SB + bn + lr];
                uint32_t b1 = Bs[(k0 + 4 + lc) * SB + bn + lr];
                #pragma unroll
                for (int mt = 0; mt < MT; mt++)
                    mma_tf32(acc[mt][nt], af[mt][0], af[mt][1], af[mt][2], af[mt][3], b0, b1);
            }
        }

        if (it + 2 < nIter) {
            load_stage((it + 2) * KT, (it + 2) % 3);
            cp_commit();
        }
    }

    // ---- epilogue ----
    #pragma unroll
    for (int mt = 0; mt < MT; mt++) {
        int rbase = row0 + warp_m * (MT * 16) + mt * 16 + lr;
        #pragma unroll
        for (int nt = 0; nt < 4; nt++) {
            int cbase = col0 + warp_n * 32 + nt * 8 + lc * 2;
            #pragma unroll
            for (int half = 0; half < 2; half++) {
                int r = rbase + half * 8;
                #pragma unroll
                for (int q = 0; q < 2; q++) {
                    int c = cbase + q;
                    if (c < Nout) {
                        float v = acc[mt][nt][half * 2 + q];
                        if (BIAS) v += bias[c];
                        if (GELU) v = gelu_f(v);
                        if (RESID) v += resid[(size_t)r * Nout + c];
                        if (RNDOUT) v = roundtf(v);
                        C[(size_t)r * Nout + c] = v;
                    }
                }
            }
        }
    }
}

#define GEMM_SMEM_BYTES(MT) (3 * ((32 * (MT)) * SA + BSZ) * 4)

// ---------------- fused flash attention (fp32, balanced causal pairing) ----------------
// grid (TT/128, BH), block 256. Each block handles query tiles bx and 15-bx
// sequentially -> every block does exactly 17 s-tile iterations.
// Output y is tf32-rounded (feeds proj GEMM A-side).
__global__ __launch_bounds__(256) void flash_attn_k(const float* __restrict__ qkv,
                                                    float* __restrict__ y) {
    __shared__ float Qt [64][64];   // [d][t]
    __shared__ float KPt[64][64];   // phase 1: K^T [d][s]; phase 2: P^T [s][t]
    __shared__ float Vs [64][64];   // [s][d]

    int bh = blockIdx.y;
    int b = bh / NH, h = bh % NH;
    int tid = threadIdx.x;
    int ty = tid >> 4, tx = tid & 15;
    const int NT2 = TT / 64;        // 16

    #pragma unroll
    for (int pass = 0; pass < 2; pass++) {
        int qt = (pass == 0) ? (int)blockIdx.x : (NT2 - 1 - (int)blockIdx.x);
        int t0 = qt * 64;

        #pragma unroll
        for (int u = 0; u < 4; u++) {
            int idx = tid + u * 256;
            int r = idx >> 4;
            int c4 = (idx & 15) * 4;
            const float* qsrc = qkv + (size_t)(b * TT + t0 + r) * (3 * CC) + h * HD + c4;
            float4 qv = *(const float4*)qsrc;
            Qt[c4 + 0][r] = qv.x;
            Qt[c4 + 1][r] = qv.y;
            Qt[c4 + 2][r] = qv.z;
            Qt[c4 + 3][r] = qv.w;
        }

        float m_i[4], l_i[4], acc[4][4];
        #pragma unroll
        for (int i = 0; i < 4; i++) {
            m_i[i] = -1e30f;
            l_i[i] = 0.f;
            #pragma unroll
            for (int j = 0; j < 4; j++) acc[i][j] = 0.f;
        }

        int nTiles = qt + 1;
        for (int st = 0; st < nTiles; st++) {
            int s0 = st * 64;

            __syncthreads();
            #pragma unroll
            for (int u = 0; u < 4; u++) {
                int idx = tid + u * 256;
                int r = idx >> 4;
                int c4 = (idx & 15) * 4;
                const float* ksrc = qkv + (size_t)(b * TT + s0 + r) * (3 * CC) + CC + h * HD + c4;
                float4 kv = *(const float4*)ksrc;
                KPt[c4 + 0][r] = kv.x;
                KPt[c4 + 1][r] = kv.y;
                KPt[c4 + 2][r] = kv.z;
                KPt[c4 + 3][r] = kv.w;
                const float* vsrc = qkv + (size_t)(b * TT + s0 + r) * (3 * CC) + 2 * CC + h * HD + c4;
                *(float4*)&Vs[r][c4] = *(const float4*)vsrc;
            }
            __syncthreads();

            float S[4][4];
            #pragma unroll
            for (int i = 0; i < 4; i++)
                #pragma unroll
                for (int j = 0; j < 4; j++) S[i][j] = 0.f;

            #pragma unroll 8
            for (int d = 0; d < 64; d++) {
                float4 aq = *(float4*)&Qt[d][ty * 4];
                float4 bq = *(float4*)&KPt[d][tx * 4];
                float av[4] = {aq.x, aq.y, aq.z, aq.w};
                float bv[4] = {bq.x, bq.y, bq.z, bq.w};
                #pragma unroll
                for (int i = 0; i < 4; i++)
                    #pragma unroll
                    for (int j = 0; j < 4; j++) S[i][j] += av[i] * bv[j];
            }

            __syncthreads();

            const float scale = 0.125f;
            bool diag = (st == qt);
            #pragma unroll
            for (int i = 0; i < 4; i++) {
                int t = t0 + ty * 4 + i;
                #pragma unroll
                for (int j = 0; j < 4; j++) {
                    float v = S[i][j] * scale;
                    if (diag && (s0 + tx * 4 + j > t)) v = -1e30f;
                    S[i][j] = v;
                }
            }

            #pragma unroll
            for (int i = 0; i < 4; i++) {
                float rmax = fmaxf(fmaxf(S[i][0], S[i][1]), fmaxf(S[i][2], S[i][3]));
                #pragma unroll
                for (int o = 8; o > 0; o >>= 1)
                    rmax = fmaxf(rmax, __shfl_xor_sync(0xffffffffu, rmax, o));
                float mnew = fmaxf(m_i[i], rmax);
                float alpha = __expf(m_i[i] - mnew);
                float rsum = 0.f;
                #pragma unroll
                for (int j = 0; j < 4; j++) {
                    float p = __expf(S[i][j] - mnew);
                    S[i][j] = p;
                    rsum += p;
                }
                #pragma unroll
                for (int o = 8; o > 0; o >>= 1)
                    rsum += __shfl_xor_sync(0xffffffffu, rsum, o);
                l_i[i] = l_i[i] * alpha + rsum;
                m_i[i] = mnew;
                #pragma unroll
                for (int j = 0; j < 4; j++) acc[i][j] *= alpha;
            }

            #pragma unroll
            for (int i = 0; i < 4; i++)
                #pragma unroll
                for (int j = 0; j < 4; j++)
                    KPt[tx * 4 + j][ty * 4 + i] = S[i][j];
            __syncthreads();

            #pragma unroll 8
            for (int k = 0; k < 64; k++) {
                float4 ap = *(float4*)&KPt[k][ty * 4];
                float4 vv = *(float4*)&Vs[k][tx * 4];
                float av[4] = {ap.x, ap.y, ap.z, ap.w};
                float bv[4] = {vv.x, vv.y, vv.z, vv.w};
                #pragma unroll
                for (int i = 0; i < 4; i++)
                    #pragma unroll
                    for (int j = 0; j < 4; j++) acc[i][j] += av[i] * bv[j];
            }
        }

        #pragma unroll
        for (int i = 0; i < 4; i++) {
            float inv = 1.f / l_i[i];
            int t = t0 + ty * 4 + i;
            float* orow = y + (size_t)(b * TT + t) * CC + h * HD;
            #pragma unroll
            for (int j = 0; j < 4; j++) orow[tx * 4 + j] = roundtf(acc[i][j] * inv);
        }
        __syncthreads();
    }
}

// ---------------- host launcher ----------------
extern "C" void kernel_launch(void* const* d_in, const int* in_sizes, int n_in,
                              void* d_out, int out_size) {
    (void)in_sizes; (void)n_in; (void)out_size;
    const int*   idx    = (const int*)  d_in[0];
    const float* wte    = (const float*)d_in[1];
    const float* wpe    = (const float*)d_in[2];
    const float* ln1_w  = (const float*)d_in[3];
    const float* ln1_b  = (const float*)d_in[4];
    const float* qkv_w  = (const float*)d_in[5];
    const float* qkv_b  = (const float*)d_in[6];
    const float* proj_w = (const float*)d_in[7];
    const float* proj_b = (const float*)d_in[8];
    const float* ln2_w  = (const float*)d_in[9];
    const float* ln2_b  = (const float*)d_in[10];
    const float* fc_w   = (const float*)d_in[11];
    const float* fc_b   = (const float*)d_in[12];
    const float* fc2_w  = (const float*)d_in[13];
    const float* fc2_b  = (const float*)d_in[14];
    const float* lnf_w  = (const float*)d_in[15];
    const float* lnf_b  = (const float*)d_in[16];
    const float* head_w = (const float*)d_in[17];
    float* out = (float*)d_out;

    float *x, *h, *qkv, *y, *m1, *wpad, *wr;
    cudaGetSymbolAddress((void**)&x,    g_x);
    cudaGetSymbolAddress((void**)&h,    g_h);
    cudaGetSymbolAddress((void**)&qkv,  g_qkv);
    cudaGetSymbolAddress((void**)&y,    g_y);
    cudaGetSymbolAddress((void**)&m1,   g_m1);
    cudaGetSymbolAddress((void**)&wpad, g_wpad);
    cudaGetSymbolAddress((void**)&wr,   g_wr);

    cudaFuncSetAttribute(tgemm_k<4, true,  false, false, false>, cudaFuncAttributeMaxDynamicSharedMemorySize, GEMM_SMEM_BYTES(4));
    cudaFuncSetAttribute(tgemm_k<4, true,  true,  false, true >, cudaFuncAttributeMaxDynamicSharedMemorySize, GEMM_SMEM_BYTES(4));
    cudaFuncSetAttribute(tgemm_k<4, false, false, false, false>, cudaFuncAttributeMaxDynamicSharedMemorySize, GEMM_SMEM_BYTES(4));
    cudaFuncSetAttribute(tgemm_k<2, true,  false, true,  false>, cudaFuncAttributeMaxDynamicSharedMemorySize, GEMM_SMEM_BYTES(2));

    float* wr_qkv  = wr + OFF_QKV;
    float* wr_proj = wr + OFF_PROJ;
    float* wr_fc   = wr + OFF_FC;
    float* wr_fc2  = wr + OFF_FC2;

    // prep: round weights to tf32 once per launch (layout unchanged [K][N])
    round_tf32_k<<<(int)((WQKV_SZ  / 4 + 255) / 256), 256>>>(qkv_w,  wr_qkv,  WQKV_SZ  / 4);
    round_tf32_k<<<(int)((WPROJ_SZ / 4 + 255) / 256), 256>>>(proj_w, wr_proj, WPROJ_SZ / 4);
    round_tf32_k<<<(int)((WFC_SZ   / 4 + 255) / 256), 256>>>(fc_w,   wr_fc,   WFC_SZ   / 4);
    round_tf32_k<<<(int)((WFC2_SZ  / 4 + 255) / 256), 256>>>(fc2_w,  wr_fc2,  WFC2_SZ  / 4);
    {
        size_t tot4 = ((size_t)CC * NPAD) / 4;
        pad_head_k<<<(int)((tot4 + 255) / 256), 256>>>(head_w, wpad);
    }

    embed_k<<<NTOK, 256>>>(idx, wte, wpe, x);

    for (int l = 0; l < LL; l++) {
        const float* l_ln1w  = ln1_w  + (size_t)l * CC;
        const float* l_ln1b  = ln1_b  + (size_t)l * CC;
        const float* l_qkvw  = wr_qkv  + (size_t)l * CC * 3 * CC;
        const float* l_qkvb  = qkv_b  + (size_t)l * 3 * CC;
        const float* l_pw    = wr_proj + (size_t)l * CC * CC;
        const float* l_pb    = proj_b + (size_t)l * CC;
        const float* l_ln2w  = ln2_w  + (size_t)l * CC;
        const float* l_ln2b  = ln2_b  + (size_t)l * CC;
        const float* l_fcw   = wr_fc   + (size_t)l * CC * 4 * CC;
        const float* l_fcb   = fc_b   + (size_t)l * 4 * CC;
        const float* l_fc2w  = wr_fc2  + (size_t)l * 4 * CC * CC;
        const float* l_fc2b  = fc2_b  + (size_t)l * CC;

        layernorm_k<<<NTOK, 256>>>(x, l_ln1w, l_ln1b, h);
        tgemm_k<4, true, false, false, false><<<dim3(NTOK / 128, (3 * CC) / 128), 256, GEMM_SMEM_BYTES(4)>>>(
            h, l_qkvw, l_qkvb, nullptr, qkv, NTOK, 3 * CC, 3 * CC, CC);
        flash_attn_k<<<dim3(TT / 128, BH), 256>>>(qkv, y);
        tgemm_k<2, true, false, true, false><<<dim3(NTOK / 64, CC / 128), 256, GEMM_SMEM_BYTES(2)>>>(
            y, l_pw, l_pb, x, x, NTOK, CC, CC, CC);
        layernorm_k<<<NTOK, 256>>>(x, l_ln2w, l_ln2b, h);
        tgemm_k<4, true, true, false, true><<<dim3(NTOK / 128, (4 * CC) / 128), 256, GEMM_SMEM_BYTES(4)>>>(
            h, l_fcw, l_fcb, nullptr, m1, NTOK, 4 * CC, 4 * CC, CC);
        tgemm_k<2, true, false, true, false><<<dim3(NTOK / 64, CC / 128), 256, GEMM_SMEM_BYTES(2)>>>(
            m1, l_fc2w, l_fc2b, x, x, NTOK, CC, CC, 4 * CC);
    }

    layernorm_k<<<NTOK, 256>>>(x, lnf_w, lnf_b, h);
    tgemm_k<4, false, false, false, false><<<dim3(NTOK / 128, NPAD / 128), 256, GEMM_SMEM_BYTES(4)>>>(
        h, wpad, nullptr, nullptr, out, NTOK, VV, NPAD, CC);
}

// round 14
// speedup vs baseline: 1.5109x; 1.1965x over previous
#include <cuda_runtime.h>
#include <math.h>
#include <stdint.h>

// ---------------- dimensions ----------------
#define BB   2
#define TT   1024
#define CC   768
#define NH   12
#define HD   64
#define LL   4
#define VV   50257
#define NPAD 50304         // 393 * 128, head_w padded columns
#define NTOK 2048          // BB*TT
#define BH   24            // BB*NH

// weight-rounding buffer offsets (floats)
#define WQKV_SZ  ((size_t)LL * CC * 3 * CC)
#define WPROJ_SZ ((size_t)LL * CC * CC)
#define WFC_SZ   ((size_t)LL * CC * 4 * CC)
#define WFC2_SZ  ((size_t)LL * 4 * CC * CC)
#define OFF_QKV  0
#define OFF_PROJ (OFF_QKV + WQKV_SZ)
#define OFF_FC   (OFF_PROJ + WPROJ_SZ)
#define OFF_FC2  (OFF_FC + WFC_SZ)
#define WR_TOTAL (OFF_FC2 + WFC2_SZ)

// ---------------- scratch (static device globals; no allocs) ----------------
__device__ float g_x  [NTOK * CC];
__device__ float g_h  [NTOK * CC];
__device__ float g_qkv[NTOK * 3 * CC];
__device__ float g_y  [NTOK * CC];
__device__ float g_m1 [NTOK * 4 * CC];
__device__ float g_wpad[(size_t)CC * NPAD];   // padded+rounded head weights [CC][NPAD]
__device__ float g_wr [WR_TOTAL];             // tf32-rounded layer weights [K][N]

// ---------------- helpers ----------------
__device__ __forceinline__ float warpReduceSum(float v) {
    #pragma unroll
    for (int o = 16; o > 0; o >>= 1) v += __shfl_xor_sync(0xffffffffu, v, o);
    return v;
}
__device__ float blockReduceSum(float v) {
    __shared__ float s[32];
    int lane = threadIdx.x & 31, wid = threadIdx.x >> 5;
    v = warpReduceSum(v);
    if (lane == 0) s[wid] = v;
    __syncthreads();
    int nw = blockDim.x >> 5;
    v = (threadIdx.x < nw) ? s[threadIdx.x] : 0.f;
    if (wid == 0) v = warpReduceSum(v);
    if (threadIdx.x == 0) s[0] = v;
    __syncthreads();
    v = s[0];
    __syncthreads();
    return v;
}

__device__ __forceinline__ float gelu_f(float x) {
    const float k = 0.7978845608028654f;  // sqrt(2/pi)
    float x3 = x * x * x;
    return 0.5f * x * (1.f + tanhf(k * (x + 0.044715f * x3)));
}

__device__ __forceinline__ uint32_t f2tf32(float x) {
    uint32_t r;
    asm("cvt.rna.tf32.f32 %0, %1;" : "=r"(r) : "f"(x));
    return r;
}
__device__ __forceinline__ float roundtf(float x) {
    return __uint_as_float(f2tf32(x));
}

__device__ __forceinline__ void mma_tf32(float c[4],
                                         uint32_t a0, uint32_t a1, uint32_t a2, uint32_t a3,
                                         uint32_t b0, uint32_t b1) {
    asm volatile(
        "mma.sync.aligned.m16n8k8.row.col.f32.tf32.tf32.f32 "
        "{%0,%1,%2,%3}, {%4,%5,%6,%7}, {%8,%9}, {%0,%1,%2,%3};\n"
        : "+f"(c[0]), "+f"(c[1]), "+f"(c[2]), "+f"(c[3])
        : "r"(a0), "r"(a1), "r"(a2), "r"(a3), "r"(b0), "r"(b1));
}

__device__ __forceinline__ void ldsm4(uint32_t r[4], uint32_t addr) {
    asm volatile("ldmatrix.sync.aligned.m8n8.x4.shared.b16 {%0,%1,%2,%3}, [%4];"
        : "=r"(r[0]), "=r"(r[1]), "=r"(r[2]), "=r"(r[3]) : "r"(addr));
}

// ---------------- cp.async helpers ----------------
__device__ __forceinline__ void cp16(uint32_t dst, const void* src) {
    asm volatile("cp.async.cg.shared.global [%0], [%1], 16;" :: "r"(dst), "l"(src));
}
__device__ __forceinline__ void cp_commit() {
    asm volatile("cp.async.commit_group;");
}
__device__ __forceinline__ void cp_wait1() {
    asm volatile("cp.async.wait_group 1;");
}
__device__ __forceinline__ void cp_wait0() {
    asm volatile("cp.async.wait_group 0;");
}

// ---------------- fused prep: round all layer weights + pad/round head ----------------
#define P_S0 (WQKV_SZ / 4)
#define P_S1 (P_S0 + WPROJ_SZ / 4)
#define P_S2 (P_S1 + WFC_SZ / 4)
#define P_S3 (P_S2 + WFC2_SZ / 4)
#define P_S4 (P_S3 + ((size_t)CC * NPAD) / 4)

__global__ void prep_k(const float* __restrict__ qkv_w, const float* __restrict__ proj_w,
                       const float* __restrict__ fc_w, const float* __restrict__ fc2_w,
                       const float* __restrict__ head_w,
                       float* __restrict__ wr, float* __restrict__ wpad) {
    size_t i = (size_t)blockIdx.x * blockDim.x + threadIdx.x;
    if (i >= P_S4) return;
    if (i < P_S3) {
        const float* src;
        float* dst;
        size_t j;
        if (i < P_S0)      { src = qkv_w;  dst = wr + OFF_QKV;  j = i; }
        else if (i < P_S1) { src = proj_w; dst = wr + OFF_PROJ; j = i - P_S0; }
        else if (i < P_S2) { src = fc_w;   dst = wr + OFF_FC;   j = i - P_S1; }
        else               { src = fc2_w;  dst = wr + OFF_FC2;  j = i - P_S2; }
        float4 v = ((const float4*)src)[j];
        v.x = roundtf(v.x); v.y = roundtf(v.y);
        v.z = roundtf(v.z); v.w = roundtf(v.w);
        ((float4*)dst)[j] = v;
    } else {
        size_t base = (i - P_S3) * 4;
        int r = (int)(base / NPAD);
        int c = (int)(base % NPAD);
        const float* src = head_w + (size_t)r * VV;
        float4 v;
        v.x = (c + 0 < VV) ? roundtf(src[c + 0]) : 0.f;
        v.y = (c + 1 < VV) ? roundtf(src[c + 1]) : 0.f;
        v.z = (c + 2 < VV) ? roundtf(src[c + 2]) : 0.f;
        v.w = (c + 3 < VV) ? roundtf(src[c + 3]) : 0.f;
        *(float4*)&wpad[base] = v;
    }
}

// ---------------- embedding ----------------
__global__ void embed_k(const int* __restrict__ idx, const float* __restrict__ wte,
                        const float* __restrict__ wpe, float* __restrict__ x) {
    int row = blockIdx.x;              // b*TT + t
    int t = row & (TT - 1);
    int tok = idx[row];
    const float* we = wte + (size_t)tok * CC;
    const float* pe = wpe + (size_t)t * CC;
    float* o = x + (size_t)row * CC;
    for (int c = threadIdx.x; c < CC; c += blockDim.x) o[c] = we[c] + pe[c];
}

// ---------------- layernorm (output tf32-rounded: feeds GEMM A-side) ----------------
__global__ void layernorm_k(const float* __restrict__ in, const float* __restrict__ w,
                            const float* __restrict__ b, float* __restrict__ out) {
    int row = blockIdx.x;
    const float* p = in + (size_t)row * CC;
    int tid = threadIdx.x;
    float v[3];
    float s = 0.f;
    #pragma unroll
    for (int i = 0; i < 3; i++) { v[i] = p[tid + i * 256]; s += v[i]; }
    float mean = blockReduceSum(s) * (1.f / (float)CC);
    float vs = 0.f;
    #pragma unroll
    for (int i = 0; i < 3; i++) { float d = v[i] - mean; vs += d * d; }
    float var = blockReduceSum(vs) * (1.f / (float)CC);
    float rstd = rsqrtf(var + 1e-5f);
    float* o = out + (size_t)row * CC;
    #pragma unroll
    for (int i = 0; i < 3; i++) {
        int c = tid + i * 256;
        o[c] = roundtf((v[i] - mean) * rstd * w[c] + b[c]);
    }
}

// ---------------- TF32 tensor-core GEMM (3-stage cp.async + A-ldmatrix) ----------------
#define KT   32
#define SA   36
#define SROWB (SA * 4)     // 144 bytes per A smem row
#define SB   136           // stride%32==8 -> B frag banks 8*lc+lr all distinct
#define BSZ  (KT * SB)

template <int MT, bool BIAS, bool GELU, bool RESID, bool RNDOUT>
__global__ __launch_bounds__(256, 2) void tgemm_k(
    const float* __restrict__ A, const float* __restrict__ B,
    const float* __restrict__ bias, const float* __restrict__ resid,
    float* __restrict__ C, int M, int Nout, int ldB, int K) {
    extern __shared__ float smem[];

    constexpr int ROWS = 32 * MT;          // A rows per block
    constexpr int ASZ  = ROWS * SA;        // floats
    constexpr int STG  = ASZ + BSZ;        // floats per stage
    constexpr uint32_t STGB = STG * 4;     // bytes per stage
    constexpr int TPR  = 256 / ROWS;       // threads per A row
    constexpr int KCH  = 32 / TPR;         // k floats per thread
    constexpr int NCPA = KCH / 4;          // cp16 per thread for A

    int tid = threadIdx.x;
    int lane = tid & 31;
    int wid = tid >> 5;
    int warp_m = wid >> 2;             // 0..1
    int warp_n = wid & 3;              // 0..3
    int lr = lane >> 2;                // 0..7
    int lc = lane & 3;                 // 0..3

    int row0 = blockIdx.x * ROWS;      // row tile on FAST grid axis (L2 B reuse)
    int col0 = blockIdx.y * 128;

    int aM  = tid / TPR;               // A row in tile
    int aK4 = (tid % TPR) * KCH;       // A k base
    int bK  = tid >> 3;                // 0..31 (B row)
    int bN4 = (tid & 7) * 4;           // B n base (+u*32)

    float acc[MT][4][4];
    #pragma unroll
    for (int i = 0; i < MT; i++)
        #pragma unroll
        for (int j = 0; j < 4; j++)
            #pragma unroll
            for (int q = 0; q < 4; q++) acc[i][j][q] = 0.f;

    const float* aSrcBase = A + (size_t)(row0 + aM) * K + aK4;
    const float* bSrcBase = B + (size_t)bK * ldB + col0 + bN4;

    uint32_t smBase = (uint32_t)__cvta_generic_to_shared(smem);

    auto load_stage = [&](int kt, int s) {
        uint32_t base = smBase + (uint32_t)s * STGB;
        {
            uint32_t dst = base + (uint32_t)(aM * SA + aK4) * 4;
            const float* src = aSrcBase + kt;
            #pragma unroll
            for (int u = 0; u < NCPA; u++)
                cp16(dst + u * 16, src + u * 4);
        }
        {
            uint32_t dst = base + (uint32_t)(ASZ + bK * SB + bN4) * 4;
            const float* src = bSrcBase + (size_t)kt * ldB;
            #pragma unroll
            for (int u = 0; u < 4; u++)
                cp16(dst + u * 32 * 4, src + u * 32);
        }
    };

    uint32_t aLane = (uint32_t)((lane & 15) * SROWB + (lane >> 4) * 16);
    uint32_t aWarpOff = (uint32_t)(warp_m * (MT * 16) * SROWB);

    int nIter = K / KT;
    load_stage(0, 0);
    cp_commit();
    load_stage(KT, 1);
    cp_commit();

    for (int it = 0; it < nIter; it++) {
        if (it + 1 < nIter) cp_wait1(); else cp_wait0();
        __syncthreads();

        uint32_t stageBase = smBase + (uint32_t)(it % 3) * STGB;
        uint32_t aBase = stageBase + aWarpOff + aLane;
        const uint32_t* Bs = (const uint32_t*)smem + (size_t)(it % 3) * STG + ASZ;

        #pragma unroll
        for (int ks = 0; ks < 4; ks++) {
            int k0 = ks * 8;
            uint32_t af[MT][4];
            #pragma unroll
            for (int mt = 0; mt < MT; mt++)
                ldsm4(af[mt], aBase + (uint32_t)(mt * 16 * SROWB + ks * 32));
            #pragma unroll
            for (int nt = 0; nt < 4; nt++) {
                int bn = warp_n * 32 + nt * 8;
                uint32_t b0 = Bs[(k0 + lc    ) * SB + bn + lr];
                uint32_t b1 = Bs[(k0 + 4 + lc) * SB + bn + lr];
                #pragma unroll
                for (int mt = 0; mt < MT; mt++)
                    mma_tf32(acc[mt][nt], af[mt][0], af[mt][1], af[mt][2], af[mt][3], b0, b1);
            }
        }

        if (it + 2 < nIter) {
            load_stage((it + 2) * KT, (it + 2) % 3);
            cp_commit();
        }
    }

    // ---- epilogue ----
    #pragma unroll
    for (int mt = 0; mt < MT; mt++) {
        int rbase = row0 + warp_m * (MT * 16) + mt * 16 + lr;
        #pragma unroll
        for (int nt = 0; nt < 4; nt++) {
            int cbase = col0 + warp_n * 32 + nt * 8 + lc * 2;
            #pragma unroll
            for (int half = 0; half < 2; half++) {
                int r = rbase + half * 8;
                #pragma unroll
                for (int q = 0; q < 2; q++) {
                    int c = cbase + q;
                    if (c < Nout) {
                        float v = acc[mt][nt][half * 2 + q];
                        if (BIAS) v += bias[c];
                        if (GELU) v = gelu_f(v);
                        if (RESID) v += resid[(size_t)r * Nout + c];
                        if (RNDOUT) v = roundtf(v);
                        C[(size_t)r * Nout + c] = v;
                    }
                }
            }
        }
    }
}

#define GEMM_SMEM_BYTES(MT) (3 * ((32 * (MT)) * SA + BSZ) * 4)

// ---------------- tensor-core flash attention ----------------
// block 128 threads (4 warps), grid (16, BH); qt = 15 - blockIdx.x (longest first).
// 64 q-rows per block (warp w owns rows w*16..w*16+15), s-tiles of 64.
// Q/K frags via verified ldmatrix mappings; V via the verified scalar B-frag path.
// Inputs qkv MUST be tf32-rounded (qkv GEMM uses RNDOUT). Output y tf32-rounded.
// Tile load: 64 rows x 64 floats; 2 threads/row x 32 floats (8 cp16 each).
#define FSTR 68    // Q / K / P smem row stride (floats); 68%32=4 -> ldsm conflict-free
#define VSTR 72    // V smem row stride; 72%32=8 -> scalar B frag conflict-free
#define FLASH_SMEM ((2 * 64 * FSTR + 64 * VSTR) * 4)

__global__ __launch_bounds__(128) void flash_attn2_k(const float* __restrict__ qkv,
                                                     float* __restrict__ y) {
    extern __shared__ float fs[];
    float* Vsf = fs + 2 * 64 * FSTR;

    int bh = blockIdx.y;
    int b = bh / NH, h = bh % NH;
    int qt = (TT / 64 - 1) - (int)blockIdx.x;   // longest blocks first
    int t0 = qt * 64;
    int tid = threadIdx.x;
    int lane = tid & 31;
    int w = tid >> 5;
    int lr = lane >> 2, lc = lane & 3;

    uint32_t qsB = (uint32_t)__cvta_generic_to_shared(fs);
    uint32_t kpB = qsB + 64 * FSTR * 4;
    uint32_t vsB = kpB + 64 * FSTR * 4;

    // tile load mapping: 64 rows, 2 threads per row, 32 floats (8x cp16) each
    int qr = tid >> 1;
    int qc = (tid & 1) * 32;

    // ---- load Q tile ----
    {
        const float* src = qkv + (size_t)(b * TT + t0 + qr) * (3 * CC) + h * HD + qc;
        uint32_t dst = qsB + (uint32_t)(qr * FSTR + qc) * 4;
        #pragma unroll
        for (int u = 0; u < 8; u++)
            cp16(dst + u * 16, src + u * 4);
        cp_commit(); cp_wait0();
    }
    __syncthreads();

    // hoist Q A-frags (8 k-steps x 4 regs)
    uint32_t qf[8][4];
    {
        uint32_t qa = qsB + (uint32_t)(w * 16 * FSTR * 4 + (lane & 15) * FSTR * 4 + (lane >> 4) * 16);
        #pragma unroll
        for (int ks = 0; ks < 8; ks++)
            ldsm4(qf[ks], qa + (uint32_t)(ks * 32));
    }

    float m_i[2] = {-1e30f, -1e30f};
    float l_i[2] = {0.f, 0.f};
    float acc[8][4];
    #pragma unroll
    for (int i = 0; i < 8; i++)
        #pragma unroll
        for (int j = 0; j < 4; j++) acc[i][j] = 0.f;

    uint32_t kb = kpB + (uint32_t)((((lane & 7) + ((lane >> 4) & 1) * 8) * FSTR) * 4 + ((lane >> 3) & 1) * 16);
    uint32_t pa = kpB + (uint32_t)(w * 16 * FSTR * 4 + (lane & 15) * FSTR * 4 + (lane >> 4) * 16);

    int nTiles = qt + 1;
    for (int st = 0; st < nTiles; st++) {
        int s0 = st * 64;

        __syncthreads();   // prior tile's KPs/Vs consumers done
        {
            const float* ksrc = qkv + (size_t)(b * TT + s0 + qr) * (3 * CC) + CC + h * HD + qc;
            uint32_t kdst = kpB + (uint32_t)(qr * FSTR + qc) * 4;
            #pragma unroll
            for (int u = 0; u < 8; u++)
                cp16(kdst + u * 16, ksrc + u * 4);
            const float* vsrc = qkv + (size_t)(b * TT + s0 + qr) * (3 * CC) + 2 * CC + h * HD + qc;
            uint32_t vdst = vsB + (uint32_t)(qr * VSTR + qc) * 4;
            #pragma unroll
            for (int u = 0; u < 8; u++)
                cp16(vdst + u * 16, vsrc + u * 4);
            cp_commit(); cp_wait0();
        }
        __syncthreads();

        // ---- S = Q K^T ----
        float S[8][4];
        #pragma unroll
        for (int i = 0; i < 8; i++)
            #pragma unroll
            for (int j = 0; j < 4; j++) S[i][j] = 0.f;

        #pragma unroll
        for (int ks = 0; ks < 8; ks++) {
            #pragma unroll
            for (int ng = 0; ng < 4; ng++) {
                uint32_t bf[4];
                ldsm4(bf, kb + (uint32_t)(ng * 16 * FSTR * 4 + ks * 32));
                mma_tf32(S[ng * 2],     qf[ks][0], qf[ks][1], qf[ks][2], qf[ks][3], bf[0], bf[1]);
                mma_tf32(S[ng * 2 + 1], qf[ks][0], qf[ks][1], qf[ks][2], qf[ks][3], bf[2], bf[3]);
            }
        }

        // ---- mask + online softmax ----
        const float scale = 0.125f;
        bool diag = (st == qt);
        #pragma unroll
        for (int half = 0; half < 2; half++) {
            int row = t0 + w * 16 + half * 8 + lr;
            float rmax = -1e30f;
            #pragma unroll
            for (int nt = 0; nt < 8; nt++) {
                #pragma unroll
                for (int q = 0; q < 2; q++) {
                    float v = S[nt][half * 2 + q] * scale;
                    if (diag && (s0 + nt * 8 + 2 * lc + q > row)) v = -1e30f;
                    S[nt][half * 2 + q] = v;
                    rmax = fmaxf(rmax, v);
                }
            }
            rmax = fmaxf(rmax, __shfl_xor_sync(0xffffffffu, rmax, 1));
            rmax = fmaxf(rmax, __shfl_xor_sync(0xffffffffu, rmax, 2));
            float mnew = fmaxf(m_i[half], rmax);
            float alpha = __expf(m_i[half] - mnew);
            float rsum = 0.f;
            #pragma unroll
            for (int nt = 0; nt < 8; nt++) {
                #pragma unroll
                for (int q = 0; q < 2; q++) {
                    float p = __expf(S[nt][half * 2 + q] - mnew);
                    S[nt][half * 2 + q] = p;
                    rsum += p;
                }
            }
            rsum += __shfl_xor_sync(0xffffffffu, rsum, 1);
            rsum += __shfl_xor_sync(0xffffffffu, rsum, 2);
            l_i[half] = l_i[half] * alpha + rsum;
            m_i[half] = mnew;
            #pragma unroll
            for (int nt = 0; nt < 8; nt++) {
                acc[nt][half * 2]     *= alpha;
                acc[nt][half * 2 + 1] *= alpha;
            }
        }

        __syncthreads();   // all warps done reading KPs (K frags) -> reuse as P

        // ---- store P (tf32-rounded) into KPs [t][s] ----
        {
            float* Ps = fs + 64 * FSTR;
            #pragma unroll
            for (int half = 0; half < 2; half++) {
                int r = w * 16 + half * 8 + lr;
                #pragma unroll
                for (int nt = 0; nt < 8; nt++) {
                    float2 pv;
                    pv.x = roundtf(S[nt][half * 2]);
                    pv.y = roundtf(S[nt][half * 2 + 1]);
                    *(float2*)&Ps[r * FSTR + nt * 8 + 2 * lc] = pv;
                }
            }
        }
        __syncwarp();

        // ---- acc += P @ V  (P rows are warp-local; V guarded by earlier barrier) ----
        #pragma unroll
        for (int ks = 0; ks < 8; ks++) {
            uint32_t pf[4];
            ldsm4(pf, pa + (uint32_t)(ks * 32));
            int k0 = ks * 8;
            #pragma unroll
            for (int nt = 0; nt < 8; nt++) {
                uint32_t b0 = __float_as_uint(Vsf[(k0 + lc    ) * VSTR + nt * 8 + lr]);
                uint32_t b1 = __float_as_uint(Vsf[(k0 + 4 + lc) * VSTR + nt * 8 + lr]);
                mma_tf32(acc[nt], pf[0], pf[1], pf[2], pf[3], b0, b1);
            }
        }
    }

    // ---- epilogue: y = acc / l ----
    #pragma unroll
    for (int half = 0; half < 2; half++) {
        float inv = 1.f / l_i[half];
        int t = t0 + w * 16 + half * 8 + lr;
        float* orow = y + (size_t)(b * TT + t) * CC + h * HD;
        #pragma unroll
        for (int nt = 0; nt < 8; nt++) {
            float2 ov;
            ov.x = roundtf(acc[nt][half * 2]     * inv);
            ov.y = roundtf(acc[nt][half * 2 + 1] * inv);
            *(float2*)&orow[nt * 8 + 2 * lc] = ov;
        }
    }
}

// ---------------- host launcher ----------------
extern "C" void kernel_launch(void* const* d_in, const int* in_sizes, int n_in,
                              void* d_out, int out_size) {
    (void)in_sizes; (void)n_in; (void)out_size;
    const int*   idx    = (const int*)  d_in[0];
    const float* wte    = (const float*)d_in[1];
    const float* wpe    = (const float*)d_in[2];
    const float* ln1_w  = (const float*)d_in[3];
    const float* ln1_b  = (const float*)d_in[4];
    const float* qkv_w  = (const float*)d_in[5];
    const float* qkv_b  = (const float*)d_in[6];
    const float* proj_w = (const float*)d_in[7];
    const float* proj_b = (const float*)d_in[8];
    const float* ln2_w  = (const float*)d_in[9];
    const float* ln2_b  = (const float*)d_in[10];
    const float* fc_w   = (const float*)d_in[11];
    const float* fc_b   = (const float*)d_in[12];
    const float* fc2_w  = (const float*)d_in[13];
    const float* fc2_b  = (const float*)d_in[14];
    const float* lnf_w  = (const float*)d_in[15];
    const float* lnf_b  = (const float*)d_in[16];
    const float* head_w = (const float*)d_in[17];
    float* out = (float*)d_out;

    float *x, *h, *qkv, *y, *m1, *wpad, *wr;
    cudaGetSymbolAddress((void**)&x,    g_x);
    cudaGetSymbolAddress((void**)&h,    g_h);
    cudaGetSymbolAddress((void**)&qkv,  g_qkv);
    cudaGetSymbolAddress((void**)&y,    g_y);
    cudaGetSymbolAddress((void**)&m1,   g_m1);
    cudaGetSymbolAddress((void**)&wpad, g_wpad);
    cudaGetSymbolAddress((void**)&wr,   g_wr);

    cudaFuncSetAttribute(tgemm_k<4, true,  false, false, true >, cudaFuncAttributeMaxDynamicSharedMemorySize, GEMM_SMEM_BYTES(4));
    cudaFuncSetAttribute(tgemm_k<4, true,  true,  false, true >, cudaFuncAttributeMaxDynamicSharedMemorySize, GEMM_SMEM_BYTES(4));
    cudaFuncSetAttribute(tgemm_k<4, false, false, false, false>, cudaFuncAttributeMaxDynamicSharedMemorySize, GEMM_SMEM_BYTES(4));
    cudaFuncSetAttribute(tgemm_k<2, true,  false, true,  false>, cudaFuncAttributeMaxDynamicSharedMemorySize, GEMM_SMEM_BYTES(2));
    cudaFuncSetAttribute(flash_attn2_k, cudaFuncAttributeMaxDynamicSharedMemorySize, FLASH_SMEM);

    float* wr_qkv  = wr + OFF_QKV;
    float* wr_proj = wr + OFF_PROJ;
    float* wr_fc   = wr + OFF_FC;
    float* wr_fc2  = wr + OFF_FC2;

    // single prep launch: round all weights + pad head
    {
        int blocks = (int)((P_S4 + 255) / 256);
        prep_k<<<blocks, 256>>>(qkv_w, proj_w, fc_w, fc2_w, head_w, wr, wpad);
    }

    embed_k<<<NTOK, 256>>>(idx, wte, wpe, x);

    for (int l = 0; l < LL; l++) {
        const float* l_ln1w  = ln1_w  + (size_t)l * CC;
        const float* l_ln1b  = ln1_b  + (size_t)l * CC;
        const float* l_qkvw  = wr_qkv  + (size_t)l * CC * 3 * CC;
        const float* l_qkvb  = qkv_b  + (size_t)l * 3 * CC;
        const float* l_pw    = wr_proj + (size_t)l * CC * CC;
        const float* l_pb    = proj_b + (size_t)l * CC;
        const float* l_ln2w  = ln2_w  + (size_t)l * CC;
        const float* l_ln2b  = ln2_b  + (size_t)l * CC;
        const float* l_fcw   = wr_fc   + (size_t)l * CC * 4 * CC;
        const float* l_fcb   = fc_b   + (size_t)l * 4 * CC;
        const float* l_fc2w  = wr_fc2  + (size_t)l * 4 * CC * CC;
        const float* l_fc2b  = fc2_b  + (size_t)l * CC;

        layernorm_k<<<NTOK, 256>>>(x, l_ln1w, l_ln1b, h);
        // qkv output tf32-rounded: flash consumes it as MMA operands
        tgemm_k<4, true, false, false, true><<<dim3(NTOK / 128, (3 * CC) / 128), 256, GEMM_SMEM_BYTES(4)>>>(
            h, l_qkvw, l_qkvb, nullptr, qkv, NTOK, 3 * CC, 3 * CC, CC);
        flash_attn2_k<<<dim3(TT / 64, BH), 128, FLASH_SMEM>>>(qkv, y);
        tgemm_k<2, true, false, true, false><<<dim3(NTOK / 64, CC / 128), 256, GEMM_SMEM_BYTES(2)>>>(
            y, l_pw, l_pb, x, x, NTOK, CC, CC, CC);
        layernorm_k<<<NTOK, 256>>>(x, l_ln2w, l_ln2b, h);
        tgemm_k<4, true, true, false, true><<<dim3(NTOK / 128, (4 * CC) / 128), 256, GEMM_SMEM_BYTES(4)>>>(
            h, l_fcw, l_fcb, nullptr, m1, NTOK, 4 * CC, 4 * CC, CC);
        tgemm_k<2, true, false, true, false><<<dim3(NTOK / 64, CC / 128), 256, GEMM_SMEM_BYTES(2)>>>(
            m1, l_fc2w, l_fc2b, x, x, NTOK, CC, CC, 4 * CC);
    }

    layernorm_k<<<NTOK, 256>>>(x, lnf_w, lnf_b, h);
    tgemm_k<4, false, false, false, false><<<dim3(NTOK / 128, NPAD / 128), 256, GEMM_SMEM_BYTES(4)>>>(
        h, wpad, nullptr, nullptr, out, NTOK, VV, NPAD, CC);
}